// round 4
// baseline (speedup 1.0000x reference)
#include <cuda_runtime.h>
#include <cuda_fp16.h>
#include <cstdint>

#define N_ROWS 524288
#define DIM 256
#define NSEG 8192
#define M_TILES 4096      // N_ROWS / 128
#define GRID_A 148

// ---------------- scratch (device globals) ----------------------------------
__device__ float    g_seg_sum[NSEG * DIM];
__device__ unsigned g_seg_max[NSEG * DIM];
__device__ int      g_counts[NSEG];
__device__ int      g_rowstart[NSEG + 1];
__device__ __half   g_W1h[DIM * DIM];
__device__ __half   g_Wph[DIM * 2 * DIM];

// ---------------- helpers ----------------------------------------------------
__device__ __forceinline__ uint32_t smem_u32(const void* p) {
    uint32_t a;
    asm("{ .reg .u64 t; cvta.to.shared.u64 t, %1; cvt.u32.u64 %0, t; }" : "=r"(a) : "l"(p));
    return a;
}
__device__ __forceinline__ void ldmat_x4(uint32_t r[4], uint32_t addr) {
    asm volatile("ldmatrix.sync.aligned.m8n8.x4.shared.b16 {%0,%1,%2,%3}, [%4];"
                 : "=r"(r[0]), "=r"(r[1]), "=r"(r[2]), "=r"(r[3]) : "r"(addr));
}
__device__ __forceinline__ void mma16816(float d[4], const uint32_t a[4],
                                         uint32_t b0, uint32_t b1) {
    asm volatile("mma.sync.aligned.m16n8k16.row.col.f32.f16.f16.f32 "
                 "{%0,%1,%2,%3}, {%4,%5,%6,%7}, {%8,%9}, {%0,%1,%2,%3};"
                 : "+f"(d[0]), "+f"(d[1]), "+f"(d[2]), "+f"(d[3])
                 : "r"(a[0]), "r"(a[1]), "r"(a[2]), "r"(a[3]), "r"(b0), "r"(b1));
}
__device__ __forceinline__ void sts8(uint32_t addr, uint32_t u0, uint32_t u1) {
    asm volatile("st.shared.v2.b32 [%0], {%1,%2};" :: "r"(addr), "r"(u0), "r"(u1) : "memory");
}
__device__ __forceinline__ void sts16(uint32_t addr, uint4 v) {
    asm volatile("st.shared.v4.b32 [%0], {%1,%2,%3,%4};"
                 :: "r"(addr), "r"(v.x), "r"(v.y), "r"(v.z), "r"(v.w) : "memory");
}

// order-preserving float <-> uint
__device__ __forceinline__ unsigned enc_f(float f) {
    unsigned i = __float_as_uint(f);
    return (i & 0x80000000u) ? ~i : (i | 0x80000000u);
}
__device__ __forceinline__ float dec_f(unsigned u) {
    return __uint_as_float((u & 0x80000000u) ? (u & 0x7FFFFFFFu) : ~u);
}

// XOR swizzle keyed on (row & 7): relocates 16B chunk within its 128B group.
#define RSWZ(row) (((uint32_t)((row) & 7)) << 4)

// ---------------- kernel A smem layout (512B rows, swizzled) ----------------
#define OFF_W    0u          // 256 * 512 = 131072
#define OFF_A    131072u     // 128 * 512 = 65536
#define OFF_HS   196608u     // 128 * 65 * 4 = 33280
#define OFF_BIAS 229888u     // 1024
#define OFF_SEG  230912u     // 512
#define SMEM_A_BYTES 231424

// ---------------- proj smem layout -------------------------------------------
#define P_OFF_B    0u        // Wp chunk: 256 x 128B = 32768
#define P_OFF_XA   32768u    // xpool chunk: 128 x 128B = 16384
#define P_OFF_OUT  49152u    // 128 x 260 x 4 = 133120
#define P_OFF_CNT  182272u   // 512
#define P_OFF_INV  182784u   // 512
#define P_OFF_BP   183296u   // 1024
#define SMEM_P_BYTES 184320
#define OUT_LD 260

// ---------------- init -------------------------------------------------------
__global__ void init_kernel() {
    int i = blockIdx.x * blockDim.x + threadIdx.x;
    if (i < NSEG * DIM) {
        g_seg_sum[i] = 0.0f;
        g_seg_max[i] = 0u;
    }
    if (i < NSEG) g_counts[i] = 0;
}

// ---------------- weight conversion fp32 -> fp16 (W1 + Wp) -------------------
__global__ void wconv_kernel(const float* __restrict__ W1, const float* __restrict__ Wp) {
    int i = blockIdx.x * 256 + threadIdx.x;   // 98304 pairs total
    if (i < 32768) {
        float2 f = ((const float2*)W1)[i];
        ((__half2*)g_W1h)[i] = __floats2half2_rn(f.x, f.y);
    } else {
        int j = i - 32768;                    // 65536 Wp pairs
        float2 f = ((const float2*)Wp)[j];
        ((__half2*)g_Wph)[j] = __floats2half2_rn(f.x, f.y);
    }
}

// ---------------- rowstart: lower_bound of each segment in sorted bidx -------
__global__ void rowstart_kernel(const int* __restrict__ bidx) {
    int s = blockIdx.x * 256 + threadIdx.x;   // 0..8191
    int lo = 0, hi = N_ROWS;
    while (lo < hi) {
        int mid = (lo + hi) >> 1;
        if (__ldg(&bidx[mid]) < s) lo = mid + 1; else hi = mid;
    }
    g_rowstart[s] = lo;
    if (s == 0) g_rowstart[NSEG] = N_ROWS;
}

// ---------------- kernel A: HMMA GEMM + segmented sum/max (pipelined) --------
__global__ void __launch_bounds__(512, 1) gemm_pool_mma(
    const float* __restrict__ x,
    const int*   __restrict__ bidx,
    const float* __restrict__ b1)
{
    extern __shared__ char smem[];
    const uint32_t sb = smem_u32(smem);
    const int t    = threadIdx.x;
    const int w    = t >> 5;
    const int lane = t & 31;
    const int wm   = w >> 2;
    const int wn   = w & 3;

    float* bias_s = (float*)(smem + OFF_BIAS);
    int*   seg_s  = (int*)(smem + OFF_SEG);
    float* hs     = (float*)(smem + OFF_HS);

    if (t < 256) bias_s[t] = b1[t];

    // ---- W1 fp16 -> SMEM [n][k] 512B rows, swizzled (once) ----
    {
        const uint4* wsrc = (const uint4*)g_W1h;   // 8192 uint4
#pragma unroll
        for (int j = 0; j < 16; j++) {
            int idx = j * 512 + t;
            int row = idx >> 5, q = idx & 31;
            uint32_t addr = (sb + OFF_W + (uint32_t)row * 512u + (uint32_t)q * 16u) ^ RSWZ(row);
            sts16(addr, wsrc[idx]);
        }
    }

    const uint32_t xmask  = RSWZ(lane);  // (lane&15)&7 == lane&7
    const uint32_t a_base = sb + OFF_A + (uint32_t)(wm * 32 + (lane & 15)) * 512u + (uint32_t)(lane >> 4) * 16u;
    const uint32_t b_base = sb + OFF_W + (uint32_t)(wn * 64 + (lane & 15)) * 512u + (uint32_t)(lane >> 4) * 16u;

    const float NEG_INF = __int_as_float(0xff800000);

    // ---- initial tile load ----
    {
        const int rowbase = blockIdx.x * 128;
        if (t < 128) seg_s[t] = bidx[rowbase + t];
        const float4* xb4 = (const float4*)(x + (size_t)rowbase * DIM);
#pragma unroll
        for (int j = 0; j < 16; j++) {
            int idx = j * 512 + t;
            int row = idx >> 6, q = idx & 63;
            float4 v = xb4[idx];
            __half2 h0 = __floats2half2_rn(v.x, v.y);
            __half2 h1 = __floats2half2_rn(v.z, v.w);
            uint32_t addr = (sb + OFF_A + (uint32_t)row * 512u + (uint32_t)q * 8u) ^ RSWZ(row);
            sts8(addr, *(uint32_t*)&h0, *(uint32_t*)&h1);
        }
    }
    __syncthreads();

    for (int tile = blockIdx.x; tile < M_TILES; tile += GRID_A) {
        // ---- HMMA mainloop: K = 256, 16 steps ----
        float acc[2][8][4];
#pragma unroll
        for (int mi = 0; mi < 2; mi++)
#pragma unroll
            for (int ni = 0; ni < 8; ni++)
#pragma unroll
                for (int d = 0; d < 4; d++) acc[mi][ni][d] = 0.0f;

#pragma unroll 4
        for (int ks = 0; ks < 16; ks++) {
            const uint32_t koff = (uint32_t)ks * 32u;
            uint32_t a0[4], a1[4];
            ldmat_x4(a0, (a_base + koff) ^ xmask);
            ldmat_x4(a1, (a_base + 16u * 512u + koff) ^ xmask);
#pragma unroll
            for (int p = 0; p < 4; p++) {
                uint32_t bf[4];
                ldmat_x4(bf, (b_base + (uint32_t)p * 8192u + koff) ^ xmask);
                mma16816(acc[0][2 * p],     a0, bf[0], bf[2]);
                mma16816(acc[0][2 * p + 1], a0, bf[1], bf[3]);
                mma16816(acc[1][2 * p],     a1, bf[0], bf[2]);
                mma16816(acc[1][2 * p + 1], a1, bf[1], bf[3]);
            }
        }

        // ---- prefetch next tile (first half) into registers ----
        const int  ntile = tile + GRID_A;
        const bool more  = ntile < M_TILES;
        const float4* xn4 = (const float4*)(x + (size_t)ntile * 128 * DIM);
        float4 pf[8];
        int segnext = 0;
        if (more) {
#pragma unroll
            for (int j = 0; j < 8; j++) pf[j] = xn4[j * 512 + t];
            if (t < 128) segnext = bidx[ntile * 128 + t];
        }

        // ---- epilogue: 4 N-chunks of 64 cols, staged in hs ----
#pragma unroll 1
        for (int ch = 0; ch < 4; ch++) {
            __syncthreads();
            if (wn == ch) {
                const int r0 = wm * 32 + (lane >> 2);
                const int c0 = 2 * (lane & 3);
#pragma unroll
                for (int mi = 0; mi < 2; mi++)
#pragma unroll
                    for (int ni = 0; ni < 8; ni++) {
                        int col = ni * 8 + c0;
                        float bb0 = bias_s[ch * 64 + col];
                        float bb1 = bias_s[ch * 64 + col + 1];
                        int rr = r0 + mi * 16;
                        hs[rr * 65 + col]           = acc[mi][ni][0] + bb0;
                        hs[rr * 65 + col + 1]       = acc[mi][ni][1] + bb1;
                        hs[(rr + 8) * 65 + col]     = acc[mi][ni][2] + bb0;
                        hs[(rr + 8) * 65 + col + 1] = acc[mi][ni][3] + bb1;
                    }
            }
            __syncthreads();

            const int col  = t & 63;
            const int g    = t >> 6;
            const int colG = ch * 64 + col;
            const int r0   = g * 16;
            const bool countLane = (ch == 0) && (col == 0);

            int   cur = seg_s[r0];
            float s   = 0.0f;
            float mx  = NEG_INF;
            int   run = 0;
#pragma unroll 4
            for (int rr = 0; rr < 16; rr++) {
                int   sg = seg_s[r0 + rr];
                float v  = hs[(r0 + rr) * 65 + col];
                if (sg != cur) {
                    atomicAdd(&g_seg_sum[cur * DIM + colG], s);
                    atomicMax(&g_seg_max[cur * DIM + colG], enc_f(mx));
                    if (countLane) atomicAdd(&g_counts[cur], run);
                    cur = sg; s = 0.0f; mx = NEG_INF; run = 0;
                }
                s += v;
                mx = fmaxf(mx, v);
                run++;
            }
            atomicAdd(&g_seg_sum[cur * DIM + colG], s);
            atomicMax(&g_seg_max[cur * DIM + colG], enc_f(mx));
            if (countLane) atomicAdd(&g_counts[cur], run);
        }

        // ---- store prefetched wave1, then load+store wave2 (A free: MMA done) ----
        if (more) {
#pragma unroll
            for (int j = 0; j < 8; j++) {
                int idx = j * 512 + t;
                int row = idx >> 6, q = idx & 63;
                __half2 h0 = __floats2half2_rn(pf[j].x, pf[j].y);
                __half2 h1 = __floats2half2_rn(pf[j].z, pf[j].w);
                uint32_t addr = (sb + OFF_A + (uint32_t)row * 512u + (uint32_t)q * 8u) ^ RSWZ(row);
                sts8(addr, *(uint32_t*)&h0, *(uint32_t*)&h1);
            }
#pragma unroll
            for (int j = 8; j < 16; j++) {
                int idx = j * 512 + t;
                int row = idx >> 6, q = idx & 63;
                float4 v = xn4[idx];
                __half2 h0 = __floats2half2_rn(v.x, v.y);
                __half2 h1 = __floats2half2_rn(v.z, v.w);
                uint32_t addr = (sb + OFF_A + (uint32_t)row * 512u + (uint32_t)q * 8u) ^ RSWZ(row);
                sts8(addr, *(uint32_t*)&h0, *(uint32_t*)&h1);
            }
        }
        __syncthreads();   // A visible to all; everyone done with seg_s/hs
        if (more && t < 128) seg_s[t] = segnext;   // read only after next epi's sync
    }
}

// ---------------- proj: HMMA fp16 GEMM + fused scatter to output -------------
// grid 64 CTAs x 512 thr; tile M=128 segs, N=256 cols, K=512 in 8 chunks of 64
__global__ void __launch_bounds__(512, 1) proj_scatter(
    const int*   __restrict__ bidx,
    const float* __restrict__ bp,
    float4*      __restrict__ out4)
{
    extern __shared__ char smem[];
    const uint32_t sb = smem_u32(smem);
    const int t    = threadIdx.x;
    const int w    = t >> 5;
    const int lane = t & 31;
    const int wm   = w >> 2;
    const int wn   = w & 3;
    const int tileM = blockIdx.x * 128;

    int*   cnt_s  = (int*)(smem + P_OFF_CNT);
    float* invc_s = (float*)(smem + P_OFF_INV);
    float* bp_s   = (float*)(smem + P_OFF_BP);
    float* outs   = (float*)(smem + P_OFF_OUT);

    if (t < 128) {
        int cn = g_counts[tileM + t];
        cnt_s[t]  = cn;
        invc_s[t] = 1.0f / (float)max(cn, 1);
    }
    if (t < 256) bp_s[t] = bp[t];

    const uint32_t xmask  = RSWZ(lane);
    const uint32_t a_base = sb + P_OFF_XA + (uint32_t)(wm * 32 + (lane & 15)) * 128u + (uint32_t)(lane >> 4) * 16u;
    const uint32_t b_base = sb + P_OFF_B  + (uint32_t)(wn * 64 + (lane & 15)) * 128u + (uint32_t)(lane >> 4) * 16u;

    float acc[2][8][4];
#pragma unroll
    for (int mi = 0; mi < 2; mi++)
#pragma unroll
        for (int ni = 0; ni < 8; ni++)
#pragma unroll
            for (int d = 0; d < 4; d++) acc[mi][ni][d] = 0.0f;

#pragma unroll 1
    for (int kc = 0; kc < 8; kc++) {
        __syncthreads();   // prev chunk MMA done; cnt/invc visible (kc=0)

        // xpool chunk: 128 rows x 64 k -> fp16 swizzled. 2048 float4 / 512 thr
#pragma unroll
        for (int i = 0; i < 4; i++) {
            int idx = i * 512 + t;
            int row = idx >> 4, q = idx & 15;
            float4 va;
            if (kc < 4) {
                va = *(const float4*)&g_seg_sum[(size_t)(tileM + row) * DIM + kc * 64 + q * 4];
                float iv = invc_s[row];
                va.x *= iv; va.y *= iv; va.z *= iv; va.w *= iv;
            } else {
                uint4 u = *(const uint4*)&g_seg_max[(size_t)(tileM + row) * DIM + (kc - 4) * 64 + q * 4];
                if (cnt_s[row] > 0) {
                    va.x = dec_f(u.x); va.y = dec_f(u.y); va.z = dec_f(u.z); va.w = dec_f(u.w);
                } else {
                    va.x = va.y = va.z = va.w = 0.0f;
                }
            }
            __half2 h0 = __floats2half2_rn(va.x, va.y);
            __half2 h1 = __floats2half2_rn(va.z, va.w);
            uint32_t addr = (sb + P_OFF_XA + (uint32_t)row * 128u + (uint32_t)q * 8u) ^ RSWZ(row);
            sts8(addr, *(uint32_t*)&h0, *(uint32_t*)&h1);
        }
        // Wp chunk: 256 rows x 64 k fp16. 2048 uint4 / 512 thr
#pragma unroll
        for (int i = 0; i < 4; i++) {
            int idx = i * 512 + t;
            int row = idx >> 3, q = idx & 7;
            uint4 v = ((const uint4*)g_Wph)[row * 64 + kc * 8 + q];
            uint32_t addr = (sb + P_OFF_B + (uint32_t)row * 128u + (uint32_t)q * 16u) ^ RSWZ(row);
            sts16(addr, v);
        }
        __syncthreads();

#pragma unroll
        for (int ks = 0; ks < 4; ks++) {
            const uint32_t koff = (uint32_t)ks * 32u;
            uint32_t a0[4], a1[4];
            ldmat_x4(a0, (a_base + koff) ^ xmask);
            ldmat_x4(a1, (a_base + 16u * 128u + koff) ^ xmask);
#pragma unroll
            for (int p = 0; p < 4; p++) {
                uint32_t bf[4];
                ldmat_x4(bf, (b_base + (uint32_t)p * 2048u + koff) ^ xmask);
                mma16816(acc[0][2 * p],     a0, bf[0], bf[2]);
                mma16816(acc[0][2 * p + 1], a0, bf[1], bf[3]);
                mma16816(acc[1][2 * p],     a1, bf[0], bf[2]);
                mma16816(acc[1][2 * p + 1], a1, bf[1], bf[3]);
            }
        }
    }

    // ---- stage out tile [128 x 256] fp32 (+bias) ----
    {
        const int r0 = wm * 32 + (lane >> 2);
        const int c0 = wn * 64 + 2 * (lane & 3);
#pragma unroll
        for (int mi = 0; mi < 2; mi++)
#pragma unroll
            for (int ni = 0; ni < 8; ni++) {
                int col = c0 + ni * 8;
                float bb0 = bp_s[col], bb1 = bp_s[col + 1];
                int rr = r0 + mi * 16;
                outs[rr * OUT_LD + col]           = acc[mi][ni][0] + bb0;
                outs[rr * OUT_LD + col + 1]       = acc[mi][ni][1] + bb1;
                outs[(rr + 8) * OUT_LD + col]     = acc[mi][ni][2] + bb0;
                outs[(rr + 8) * OUT_LD + col + 1] = acc[mi][ni][3] + bb1;
            }
    }
    __syncthreads();

    // ---- scatter: rows [rowstart(tileM), rowstart(tileM+128)) of d_out ----
    const int rstart = g_rowstart[tileM];
    const int rend   = g_rowstart[tileM + 128];
    const int cq     = t & 63;           // float4 column
    for (int r = rstart + (t >> 6); r < rend; r += 8) {
        int localseg = __ldg(&bidx[r]) - tileM;
        float4 v = *(const float4*)&outs[localseg * OUT_LD + cq * 4];
        out4[(size_t)r * 64 + cq] = v;
    }
}

// ---------------- launch -----------------------------------------------------
extern "C" void kernel_launch(void* const* d_in, const int* in_sizes, int n_in,
                              void* d_out, int out_size) {
    const float* x    = (const float*)d_in[0];
    const int*   bidx = (const int*)  d_in[1];
    const float* W1   = (const float*)d_in[2];
    const float* b1   = (const float*)d_in[3];
    const float* Wp   = (const float*)d_in[4];
    const float* bp   = (const float*)d_in[5];

    cudaFuncSetAttribute(gemm_pool_mma, cudaFuncAttributeMaxDynamicSharedMemorySize,
                         SMEM_A_BYTES);
    cudaFuncSetAttribute(proj_scatter, cudaFuncAttributeMaxDynamicSharedMemorySize,
                         SMEM_P_BYTES);

    init_kernel<<<(NSEG * DIM + 255) / 256, 256>>>();
    wconv_kernel<<<384, 256>>>(W1, Wp);
    rowstart_kernel<<<NSEG / 256, 256>>>(bidx);

    gemm_pool_mma<<<GRID_A, 512, SMEM_A_BYTES>>>(x, bidx, b1);

    proj_scatter<<<NSEG / 128, 512, SMEM_P_BYTES>>>(bidx, bp, (float4*)d_out);
}

// round 5
// speedup vs baseline: 1.1083x; 1.1083x over previous
#include <cuda_runtime.h>
#include <cuda_fp16.h>
#include <cstdint>

#define N_ROWS 524288
#define DIM 256
#define NSEG 8192
#define M_TILES 4096      // N_ROWS / 128
#define GRID_A 148

// ---------------- scratch (device globals) ----------------------------------
__device__ float    g_seg_sum[NSEG * DIM];
__device__ unsigned g_seg_max[NSEG * DIM];
__device__ int      g_counts[NSEG];
__device__ int      g_rowstart[NSEG + 1];
__device__ __half   g_W1h[DIM * DIM];
__device__ __half   g_Wph[DIM * 2 * DIM];

// ---------------- helpers ----------------------------------------------------
__device__ __forceinline__ uint32_t smem_u32(const void* p) {
    uint32_t a;
    asm("{ .reg .u64 t; cvta.to.shared.u64 t, %1; cvt.u32.u64 %0, t; }" : "=r"(a) : "l"(p));
    return a;
}
__device__ __forceinline__ void ldmat_x4(uint32_t r[4], uint32_t addr) {
    asm volatile("ldmatrix.sync.aligned.m8n8.x4.shared.b16 {%0,%1,%2,%3}, [%4];"
                 : "=r"(r[0]), "=r"(r[1]), "=r"(r[2]), "=r"(r[3]) : "r"(addr));
}
__device__ __forceinline__ void mma16816(float d[4], const uint32_t a[4],
                                         uint32_t b0, uint32_t b1) {
    asm volatile("mma.sync.aligned.m16n8k16.row.col.f32.f16.f16.f32 "
                 "{%0,%1,%2,%3}, {%4,%5,%6,%7}, {%8,%9}, {%0,%1,%2,%3};"
                 : "+f"(d[0]), "+f"(d[1]), "+f"(d[2]), "+f"(d[3])
                 : "r"(a[0]), "r"(a[1]), "r"(a[2]), "r"(a[3]), "r"(b0), "r"(b1));
}
__device__ __forceinline__ void sts8(uint32_t addr, uint32_t u0, uint32_t u1) {
    asm volatile("st.shared.v2.b32 [%0], {%1,%2};" :: "r"(addr), "r"(u0), "r"(u1) : "memory");
}
__device__ __forceinline__ void sts16(uint32_t addr, uint4 v) {
    asm volatile("st.shared.v4.b32 [%0], {%1,%2,%3,%4};"
                 :: "r"(addr), "r"(v.x), "r"(v.y), "r"(v.z), "r"(v.w) : "memory");
}

// order-preserving float <-> uint
__device__ __forceinline__ unsigned enc_f(float f) {
    unsigned i = __float_as_uint(f);
    return (i & 0x80000000u) ? ~i : (i | 0x80000000u);
}
__device__ __forceinline__ float dec_f(unsigned u) {
    return __uint_as_float((u & 0x80000000u) ? (u & 0x7FFFFFFFu) : ~u);
}

// XOR swizzle keyed on (row & 7): relocates 16B chunk within its 128B group.
#define RSWZ(row) (((uint32_t)((row) & 7)) << 4)

// ---------------- kernel A smem layout (512B rows, swizzled) ----------------
#define OFF_W    0u          // 256 * 512 = 131072
#define OFF_A    131072u     // 128 * 512 = 65536
#define OFF_HS   196608u     // 128 * 65 * 4 = 33280
#define OFF_BIAS 229888u     // 1024
#define OFF_SEG  230912u     // 512
#define SMEM_A_BYTES 231424

// ---------------- proj smem layout -------------------------------------------
#define P_OFF_B    0u        // Wp chunk: 256 x 128B = 32768
#define P_OFF_XA   32768u    // xpool chunk: 128 x 128B = 16384
#define P_OFF_OUT  49152u    // 128 x 260 x 4 = 133120
#define P_OFF_CNT  182272u   // 512
#define P_OFF_INV  182784u   // 512
#define P_OFF_BP   183296u   // 1024
#define SMEM_P_BYTES 184320
#define OUT_LD 260

// ---------------- init -------------------------------------------------------
__global__ void init_kernel() {
    int i = blockIdx.x * blockDim.x + threadIdx.x;
    if (i < NSEG * DIM) {
        g_seg_sum[i] = 0.0f;
        g_seg_max[i] = 0u;
    }
    if (i < NSEG) g_counts[i] = 0;
}

// ---------------- weight conversion fp32 -> fp16 (W1 + Wp) -------------------
__global__ void wconv_kernel(const float* __restrict__ W1, const float* __restrict__ Wp) {
    int i = blockIdx.x * 256 + threadIdx.x;   // 98304 pairs total
    if (i < 32768) {
        float2 f = ((const float2*)W1)[i];
        ((__half2*)g_W1h)[i] = __floats2half2_rn(f.x, f.y);
    } else {
        int j = i - 32768;                    // 65536 Wp pairs
        float2 f = ((const float2*)Wp)[j];
        ((__half2*)g_Wph)[j] = __floats2half2_rn(f.x, f.y);
    }
}

// ---------------- rowstart: lower_bound of each segment in sorted bidx -------
__global__ void rowstart_kernel(const int* __restrict__ bidx) {
    int s = blockIdx.x * 256 + threadIdx.x;   // 0..8191
    int lo = 0, hi = N_ROWS;
    while (lo < hi) {
        int mid = (lo + hi) >> 1;
        if (__ldg(&bidx[mid]) < s) lo = mid + 1; else hi = mid;
    }
    g_rowstart[s] = lo;
    if (s == 0) g_rowstart[NSEG] = N_ROWS;
}

// ---------------- kernel A: HMMA GEMM (h = x W1^T + b1) + segmented sum/max -
// persistent, 512 threads = 16 warps in 4x4 grid; warp tile 32(M) x 64(N)
__global__ void __launch_bounds__(512, 1) gemm_pool_mma(
    const float* __restrict__ x,
    const int*   __restrict__ bidx,
    const float* __restrict__ b1)
{
    extern __shared__ char smem[];
    const uint32_t sb = smem_u32(smem);
    const int t    = threadIdx.x;
    const int w    = t >> 5;
    const int lane = t & 31;
    const int wm   = w >> 2;
    const int wn   = w & 3;

    float* bias_s = (float*)(smem + OFF_BIAS);
    int*   seg_s  = (int*)(smem + OFF_SEG);
    float* hs     = (float*)(smem + OFF_HS);

    if (t < 256) bias_s[t] = b1[t];

    // ---- W1 fp16 -> SMEM [n][k] 512B rows, swizzled (once per CTA) ----
    {
        const uint4* wsrc = (const uint4*)g_W1h;   // 8192 uint4
#pragma unroll
        for (int j = 0; j < 16; j++) {
            int idx = j * 512 + t;
            int row = idx >> 5, q = idx & 31;
            uint32_t addr = (sb + OFF_W + (uint32_t)row * 512u + (uint32_t)q * 16u) ^ RSWZ(row);
            sts16(addr, wsrc[idx]);
        }
    }

    const uint32_t xmask  = RSWZ(lane);
    const uint32_t a_base = sb + OFF_A + (uint32_t)(wm * 32 + (lane & 15)) * 512u + (uint32_t)(lane >> 4) * 16u;
    const uint32_t b_base = sb + OFF_W + (uint32_t)(wn * 64 + (lane & 15)) * 512u + (uint32_t)(lane >> 4) * 16u;

    const float NEG_INF = __int_as_float(0xff800000);

    for (int tile = blockIdx.x; tile < M_TILES; tile += GRID_A) {
        const int rowbase = tile * 128;
        __syncthreads();   // prior epilogue done with hs/seg before overwrite

        if (t < 128) seg_s[t] = bidx[rowbase + t];

        // ---- load x tile fp32 -> fp16 -> SMEM [m][k] swizzled ----
        {
            const float4* xb4 = (const float4*)(x + (size_t)rowbase * DIM);
#pragma unroll
            for (int j = 0; j < 16; j++) {
                int idx = j * 512 + t;
                int row = idx >> 6, q = idx & 63;
                float4 v = xb4[idx];
                __half2 h0 = __floats2half2_rn(v.x, v.y);
                __half2 h1 = __floats2half2_rn(v.z, v.w);
                uint32_t addr = (sb + OFF_A + (uint32_t)row * 512u + (uint32_t)q * 8u) ^ RSWZ(row);
                sts8(addr, *(uint32_t*)&h0, *(uint32_t*)&h1);
            }
        }
        __syncthreads();

        // ---- HMMA mainloop: K = 256 in 16 steps of 16 ----
        float acc[2][8][4];
#pragma unroll
        for (int mi = 0; mi < 2; mi++)
#pragma unroll
            for (int ni = 0; ni < 8; ni++)
#pragma unroll
                for (int d = 0; d < 4; d++) acc[mi][ni][d] = 0.0f;

#pragma unroll 4
        for (int ks = 0; ks < 16; ks++) {
            const uint32_t koff = (uint32_t)ks * 32u;
            uint32_t a0[4], a1[4];
            ldmat_x4(a0, (a_base + koff) ^ xmask);
            ldmat_x4(a1, (a_base + 16u * 512u + koff) ^ xmask);
#pragma unroll
            for (int p = 0; p < 4; p++) {
                uint32_t bf[4];
                ldmat_x4(bf, (b_base + (uint32_t)p * 8192u + koff) ^ xmask);
                mma16816(acc[0][2 * p],     a0, bf[0], bf[2]);
                mma16816(acc[0][2 * p + 1], a0, bf[1], bf[3]);
                mma16816(acc[1][2 * p],     a1, bf[0], bf[2]);
                mma16816(acc[1][2 * p + 1], a1, bf[1], bf[3]);
            }
        }

        // ---- epilogue: 4 N-chunks of 64 cols; stage in hs ----
#pragma unroll 1
        for (int ch = 0; ch < 4; ch++) {
            __syncthreads();
            if (wn == ch) {
                const int r0 = wm * 32 + (lane >> 2);
                const int c0 = 2 * (lane & 3);
#pragma unroll
                for (int mi = 0; mi < 2; mi++)
#pragma unroll
                    for (int ni = 0; ni < 8; ni++) {
                        int col = ni * 8 + c0;
                        float bb0 = bias_s[ch * 64 + col];
                        float bb1 = bias_s[ch * 64 + col + 1];
                        int rr = r0 + mi * 16;
                        hs[rr * 65 + col]           = acc[mi][ni][0] + bb0;
                        hs[rr * 65 + col + 1]       = acc[mi][ni][1] + bb1;
                        hs[(rr + 8) * 65 + col]     = acc[mi][ni][2] + bb0;
                        hs[(rr + 8) * 65 + col + 1] = acc[mi][ni][3] + bb1;
                    }
            }
            __syncthreads();

            // sorted-run segmented reduce: 8 groups x 16 rows, 64 cols
            const int col  = t & 63;
            const int g    = t >> 6;
            const int colG = ch * 64 + col;
            const int r0   = g * 16;
            const bool countLane = (ch == 0) && (col == 0);

            int   cur = seg_s[r0];
            float s   = 0.0f;
            float mx  = NEG_INF;
            int   run = 0;
#pragma unroll 4
            for (int rr = 0; rr < 16; rr++) {
                int   sg = seg_s[r0 + rr];
                float v  = hs[(r0 + rr) * 65 + col];
                if (sg != cur) {
                    atomicAdd(&g_seg_sum[cur * DIM + colG], s);
                    atomicMax(&g_seg_max[cur * DIM + colG], enc_f(mx));
                    if (countLane) atomicAdd(&g_counts[cur], run);
                    cur = sg; s = 0.0f; mx = NEG_INF; run = 0;
                }
                s += v;
                mx = fmaxf(mx, v);
                run++;
            }
            atomicAdd(&g_seg_sum[cur * DIM + colG], s);
            atomicMax(&g_seg_max[cur * DIM + colG], enc_f(mx));
            if (countLane) atomicAdd(&g_counts[cur], run);
        }
    }
}

// ---------------- proj: HMMA fp16 GEMM + fused MLP-4 scatter to output -------
// grid 64 CTAs x 512 thr; tile M=128 segs, N=256 cols, K=512 in 8 chunks of 64
__global__ void __launch_bounds__(512, 1) proj_scatter(
    const int*   __restrict__ bidx,
    const float* __restrict__ bp,
    float4*      __restrict__ out4)
{
    extern __shared__ char smem[];
    const uint32_t sb = smem_u32(smem);
    const int t    = threadIdx.x;
    const int w    = t >> 5;
    const int lane = t & 31;
    const int wm   = w >> 2;
    const int wn   = w & 3;
    const int tileM = blockIdx.x * 128;

    int*   cnt_s  = (int*)(smem + P_OFF_CNT);
    float* invc_s = (float*)(smem + P_OFF_INV);
    float* bp_s   = (float*)(smem + P_OFF_BP);
    float* outs   = (float*)(smem + P_OFF_OUT);

    if (t < 128) {
        int cn = g_counts[tileM + t];
        cnt_s[t]  = cn;
        invc_s[t] = 1.0f / (float)max(cn, 1);
    }
    if (t < 256) bp_s[t] = bp[t];

    const uint32_t xmask  = RSWZ(lane);
    const uint32_t a_base = sb + P_OFF_XA + (uint32_t)(wm * 32 + (lane & 15)) * 128u + (uint32_t)(lane >> 4) * 16u;
    const uint32_t b_base = sb + P_OFF_B  + (uint32_t)(wn * 64 + (lane & 15)) * 128u + (uint32_t)(lane >> 4) * 16u;

    float acc[2][8][4];
#pragma unroll
    for (int mi = 0; mi < 2; mi++)
#pragma unroll
        for (int ni = 0; ni < 8; ni++)
#pragma unroll
            for (int d = 0; d < 4; d++) acc[mi][ni][d] = 0.0f;

#pragma unroll 1
    for (int kc = 0; kc < 8; kc++) {
        __syncthreads();   // prev chunk MMA done; cnt/invc visible (kc=0)

        // xpool chunk: 128 rows x 64 k -> fp16 swizzled. 2048 float4 / 512 thr
#pragma unroll
        for (int i = 0; i < 4; i++) {
            int idx = i * 512 + t;
            int row = idx >> 4, q = idx & 15;
            float4 va;
            if (kc < 4) {
                va = *(const float4*)&g_seg_sum[(size_t)(tileM + row) * DIM + kc * 64 + q * 4];
                float iv = invc_s[row];
                va.x *= iv; va.y *= iv; va.z *= iv; va.w *= iv;
            } else {
                uint4 u = *(const uint4*)&g_seg_max[(size_t)(tileM + row) * DIM + (kc - 4) * 64 + q * 4];
                if (cnt_s[row] > 0) {
                    va.x = dec_f(u.x); va.y = dec_f(u.y); va.z = dec_f(u.z); va.w = dec_f(u.w);
                } else {
                    va.x = va.y = va.z = va.w = 0.0f;
                }
            }
            __half2 h0 = __floats2half2_rn(va.x, va.y);
            __half2 h1 = __floats2half2_rn(va.z, va.w);
            uint32_t addr = (sb + P_OFF_XA + (uint32_t)row * 128u + (uint32_t)q * 8u) ^ RSWZ(row);
            sts8(addr, *(uint32_t*)&h0, *(uint32_t*)&h1);
        }
        // Wp chunk: 256 rows x 64 k fp16. 2048 uint4 / 512 thr
#pragma unroll
        for (int i = 0; i < 4; i++) {
            int idx = i * 512 + t;
            int row = idx >> 3, q = idx & 7;
            uint4 v = ((const uint4*)g_Wph)[row * 64 + kc * 8 + q];
            uint32_t addr = (sb + P_OFF_B + (uint32_t)row * 128u + (uint32_t)q * 16u) ^ RSWZ(row);
            sts16(addr, v);
        }
        __syncthreads();

#pragma unroll
        for (int ks = 0; ks < 4; ks++) {
            const uint32_t koff = (uint32_t)ks * 32u;
            uint32_t a0[4], a1[4];
            ldmat_x4(a0, (a_base + koff) ^ xmask);
            ldmat_x4(a1, (a_base + 16u * 128u + koff) ^ xmask);
#pragma unroll
            for (int p = 0; p < 4; p++) {
                uint32_t bf[4];
                ldmat_x4(bf, (b_base + (uint32_t)p * 2048u + koff) ^ xmask);
                mma16816(acc[0][2 * p],     a0, bf[0], bf[2]);
                mma16816(acc[0][2 * p + 1], a0, bf[1], bf[3]);
                mma16816(acc[1][2 * p],     a1, bf[0], bf[2]);
                mma16816(acc[1][2 * p + 1], a1, bf[1], bf[3]);
            }
        }
    }

    // ---- stage out tile [128 x 256] fp32 (+bias) ----
    {
        const int r0 = wm * 32 + (lane >> 2);
        const int c0 = wn * 64 + 2 * (lane & 3);
#pragma unroll
        for (int mi = 0; mi < 2; mi++)
#pragma unroll
            for (int ni = 0; ni < 8; ni++) {
                int col = c0 + ni * 8;
                float bb0 = bp_s[col], bb1 = bp_s[col + 1];
                int rr = r0 + mi * 16;
                outs[rr * OUT_LD + col]           = acc[mi][ni][0] + bb0;
                outs[rr * OUT_LD + col + 1]       = acc[mi][ni][1] + bb1;
                outs[(rr + 8) * OUT_LD + col]     = acc[mi][ni][2] + bb0;
                outs[(rr + 8) * OUT_LD + col + 1] = acc[mi][ni][3] + bb1;
            }
    }
    __syncthreads();

    // ---- scatter rows [rowstart(tileM), rowstart(tileM+128)) with MLP=4 ----
    const int rstart = g_rowstart[tileM];
    const int rend   = g_rowstart[tileM + 128];
    const int cq     = t & 63;           // float4 column
    int r = rstart + (t >> 6);           // 8 row-lanes, stride 8
    for (; r + 24 < rend; r += 32) {
        int s0 = __ldg(&bidx[r])      - tileM;
        int s1 = __ldg(&bidx[r +  8]) - tileM;
        int s2 = __ldg(&bidx[r + 16]) - tileM;
        int s3 = __ldg(&bidx[r + 24]) - tileM;
        float4 v0 = *(const float4*)&outs[s0 * OUT_LD + cq * 4];
        float4 v1 = *(const float4*)&outs[s1 * OUT_LD + cq * 4];
        float4 v2 = *(const float4*)&outs[s2 * OUT_LD + cq * 4];
        float4 v3 = *(const float4*)&outs[s3 * OUT_LD + cq * 4];
        out4[(size_t)r * 64 + cq]        = v0;
        out4[(size_t)(r +  8) * 64 + cq] = v1;
        out4[(size_t)(r + 16) * 64 + cq] = v2;
        out4[(size_t)(r + 24) * 64 + cq] = v3;
    }
    for (; r < rend; r += 8) {
        int s0 = __ldg(&bidx[r]) - tileM;
        out4[(size_t)r * 64 + cq] = *(const float4*)&outs[s0 * OUT_LD + cq * 4];
    }
}

// ---------------- launch -----------------------------------------------------
extern "C" void kernel_launch(void* const* d_in, const int* in_sizes, int n_in,
                              void* d_out, int out_size) {
    const float* x    = (const float*)d_in[0];
    const int*   bidx = (const int*)  d_in[1];
    const float* W1   = (const float*)d_in[2];
    const float* b1   = (const float*)d_in[3];
    const float* Wp   = (const float*)d_in[4];
    const float* bp   = (const float*)d_in[5];

    cudaFuncSetAttribute(gemm_pool_mma, cudaFuncAttributeMaxDynamicSharedMemorySize,
                         SMEM_A_BYTES);
    cudaFuncSetAttribute(proj_scatter, cudaFuncAttributeMaxDynamicSharedMemorySize,
                         SMEM_P_BYTES);

    init_kernel<<<(NSEG * DIM + 255) / 256, 256>>>();
    wconv_kernel<<<384, 256>>>(W1, Wp);
    rowstart_kernel<<<NSEG / 256, 256>>>(bidx);

    gemm_pool_mma<<<GRID_A, 512, SMEM_A_BYTES>>>(x, bidx, b1);

    proj_scatter<<<NSEG / 128, 512, SMEM_P_BYTES>>>(bidx, bp, (float4*)d_out);
}

// round 7
// speedup vs baseline: 1.1811x; 1.0657x over previous
#include <cuda_runtime.h>
#include <cuda_fp16.h>
#include <cstdint>

#define N_ROWS 524288
#define DIM 256
#define NSEG 8192
#define MT 8192           // 64-row M tiles
#define GRID_A 296        // 2 CTAs per SM

// ---------------- scratch (device globals) ----------------------------------
__device__ float    g_seg_sum[NSEG * DIM];
__device__ unsigned g_seg_max[NSEG * DIM];
__device__ int      g_counts[NSEG];
__device__ int      g_rowstart[NSEG + 1];
__device__ __half   g_W1h[DIM * DIM];
__device__ __half   g_Wph[DIM * 2 * DIM];

// ---------------- helpers ----------------------------------------------------
__device__ __forceinline__ uint32_t smem_u32(const void* p) {
    uint32_t a;
    asm("{ .reg .u64 t; cvta.to.shared.u64 t, %1; cvt.u32.u64 %0, t; }" : "=r"(a) : "l"(p));
    return a;
}
__device__ __forceinline__ void ldmat_x4(uint32_t r[4], uint32_t addr) {
    asm volatile("ldmatrix.sync.aligned.m8n8.x4.shared.b16 {%0,%1,%2,%3}, [%4];"
                 : "=r"(r[0]), "=r"(r[1]), "=r"(r[2]), "=r"(r[3]) : "r"(addr));
}
__device__ __forceinline__ void mma16816(float d[4], const uint32_t a[4],
                                         uint32_t b0, uint32_t b1) {
    asm volatile("mma.sync.aligned.m16n8k16.row.col.f32.f16.f16.f32 "
                 "{%0,%1,%2,%3}, {%4,%5,%6,%7}, {%8,%9}, {%0,%1,%2,%3};"
                 : "+f"(d[0]), "+f"(d[1]), "+f"(d[2]), "+f"(d[3])
                 : "r"(a[0]), "r"(a[1]), "r"(a[2]), "r"(a[3]), "r"(b0), "r"(b1));
}
__device__ __forceinline__ void sts8(uint32_t addr, uint32_t u0, uint32_t u1) {
    asm volatile("st.shared.v2.b32 [%0], {%1,%2};" :: "r"(addr), "r"(u0), "r"(u1) : "memory");
}
__device__ __forceinline__ void sts16(uint32_t addr, uint4 v) {
    asm volatile("st.shared.v4.b32 [%0], {%1,%2,%3,%4};"
                 :: "r"(addr), "r"(v.x), "r"(v.y), "r"(v.z), "r"(v.w) : "memory");
}
__device__ __forceinline__ unsigned enc_f(float f) {
    unsigned i = __float_as_uint(f);
    return (i & 0x80000000u) ? ~i : (i | 0x80000000u);
}
__device__ __forceinline__ float dec_f(unsigned u) {
    return __uint_as_float((u & 0x80000000u) ? (u & 0x7FFFFFFFu) : ~u);
}
#define RSWZ(row) (((uint32_t)((row) & 7)) << 4)

// ---------------- kernel A smem layout (per CTA, ~105 KB) --------------------
#define OFF_W    0u          // 128 rows x 512B = 65536
#define OFF_A    65536u      // 64 rows x 512B  = 32768
#define OFF_HS   98304u      // 64 x 33 x 4     = 8448
#define OFF_BIAS 106752u     // 128 floats      = 512
#define OFF_SEG  107264u     // 64 ints         = 256
#define SMEM_A_BYTES 107520

// ---------------- proj smem layout (tile M=64) --------------------------------
#define P_OFF_B    0u        // Wp chunk: 256 x 128B = 32768
#define P_OFF_XA   32768u    // xpool chunk: 64 x 128B = 8192
#define P_OFF_OUT  40960u    // 64 x 260 x 4 = 66560
#define P_OFF_CNT  107520u   // 256
#define P_OFF_INV  107776u   // 256
#define P_OFF_BP   108032u   // 1024
#define SMEM_P_BYTES 109056
#define OUT_LD 260

// ---------------- init -------------------------------------------------------
__global__ void init_kernel() {
    int i = blockIdx.x * blockDim.x + threadIdx.x;
    if (i < NSEG * DIM) {
        g_seg_sum[i] = 0.0f;
        g_seg_max[i] = 0u;
    }
    if (i < NSEG) g_counts[i] = 0;
}

// ---------------- weight conversion fp32 -> fp16 (W1 + Wp) -------------------
__global__ void wconv_kernel(const float* __restrict__ W1, const float* __restrict__ Wp) {
    int i = blockIdx.x * 256 + threadIdx.x;
    if (i < 32768) {
        float2 f = ((const float2*)W1)[i];
        ((__half2*)g_W1h)[i] = __floats2half2_rn(f.x, f.y);
    } else {
        int j = i - 32768;
        float2 f = ((const float2*)Wp)[j];
        ((__half2*)g_Wph)[j] = __floats2half2_rn(f.x, f.y);
    }
}

// ---------------- rowstart: lower_bound of each segment in sorted bidx -------
__global__ void rowstart_kernel(const int* __restrict__ bidx) {
    int s = blockIdx.x * 256 + threadIdx.x;
    int lo = 0, hi = N_ROWS;
    while (lo < hi) {
        int mid = (lo + hi) >> 1;
        if (__ldg(&bidx[mid]) < s) lo = mid + 1; else hi = mid;
    }
    g_rowstart[s] = lo;
    if (s == 0) g_rowstart[NSEG] = N_ROWS;
}

// ---------------- kernel A: HMMA GEMM + segmented sum/max, 2 CTAs/SM ---------
// CTA parity = N-half (128 cols). Tile: 64 rows x 128 cols. 8 warps (2M x 4N),
// warp tile 32x32.
__global__ void __launch_bounds__(256, 2) gemm_pool_mma(
    const float* __restrict__ x,
    const int*   __restrict__ bidx,
    const float* __restrict__ b1)
{
    extern __shared__ char smem[];
    const uint32_t sb = smem_u32(smem);
    const int t     = threadIdx.x;
    const int w     = t >> 5;
    const int lane  = t & 31;
    const int wm    = w >> 2;        // 0..1
    const int wn    = w & 3;         // 0..3
    const int nhalf = blockIdx.x & 1;
    const int nbase = nhalf * 128;

    float* bias_s = (float*)(smem + OFF_BIAS);
    int*   seg_s  = (int*)(smem + OFF_SEG);
    float* hs     = (float*)(smem + OFF_HS);

    if (t < 128) bias_s[t] = b1[nbase + t];

    // ---- W half fp16 -> SMEM [n][k] 512B rows, swizzled (once per CTA) ----
    {
        const uint4* wsrc = (const uint4*)g_W1h + (size_t)nbase * 32;  // 4096 uint4
#pragma unroll
        for (int j = 0; j < 16; j++) {
            int idx = j * 256 + t;
            int row = idx >> 5, q = idx & 31;
            uint32_t addr = (sb + OFF_W + (uint32_t)row * 512u + (uint32_t)q * 16u) ^ RSWZ(row);
            sts16(addr, wsrc[idx]);
        }
    }

    const uint32_t xmask  = RSWZ(lane);
    const uint32_t a_base = sb + OFF_A + (uint32_t)(wm * 32 + (lane & 15)) * 512u + (uint32_t)(lane >> 4) * 16u;
    const uint32_t b_base = sb + OFF_W + (uint32_t)(wn * 32 + (lane & 15)) * 512u + (uint32_t)(lane >> 4) * 16u;

    const float NEG_INF = __int_as_float(0xff800000);

    for (int m = (blockIdx.x >> 1); m < MT; m += 148) {
        const int rowbase = m * 64;
        __syncthreads();   // prior epilogue done with hs/seg; A free

        if (t < 64) seg_s[t] = bidx[rowbase + t];

        // ---- load x tile fp32 -> fp16 -> SMEM [64][256] swizzled ----
        {
            const float4* xb4 = (const float4*)(x + (size_t)rowbase * DIM);
#pragma unroll
            for (int j = 0; j < 16; j++) {
                int idx = j * 256 + t;
                int row = idx >> 6, q = idx & 63;
                float4 v = xb4[idx];
                __half2 h0 = __floats2half2_rn(v.x, v.y);
                __half2 h1 = __floats2half2_rn(v.z, v.w);
                uint32_t addr = (sb + OFF_A + (uint32_t)row * 512u + (uint32_t)q * 8u) ^ RSWZ(row);
                sts8(addr, *(uint32_t*)&h0, *(uint32_t*)&h1);
            }
        }
        __syncthreads();

        // ---- HMMA mainloop: K = 256 in 16 steps ----
        float acc[2][4][4];
#pragma unroll
        for (int mi = 0; mi < 2; mi++)
#pragma unroll
            for (int ni = 0; ni < 4; ni++)
#pragma unroll
                for (int d = 0; d < 4; d++) acc[mi][ni][d] = 0.0f;

#pragma unroll 4
        for (int ks = 0; ks < 16; ks++) {
            const uint32_t koff = (uint32_t)ks * 32u;
            uint32_t a0[4], a1[4];
            ldmat_x4(a0, (a_base + koff) ^ xmask);
            ldmat_x4(a1, (a_base + 16u * 512u + koff) ^ xmask);
#pragma unroll
            for (int p = 0; p < 2; p++) {
                uint32_t bf[4];
                ldmat_x4(bf, (b_base + (uint32_t)p * (16u * 512u) + koff) ^ xmask);
                mma16816(acc[0][2 * p],     a0, bf[0], bf[2]);
                mma16816(acc[0][2 * p + 1], a0, bf[1], bf[3]);
                mma16816(acc[1][2 * p],     a1, bf[0], bf[2]);
                mma16816(acc[1][2 * p + 1], a1, bf[1], bf[3]);
            }
        }

        // ---- epilogue: 4 chunks of 32 cols ----
#pragma unroll 1
        for (int ch = 0; ch < 4; ch++) {
            __syncthreads();
            if (wn == ch) {
                const int r0 = wm * 32 + (lane >> 2);
                const int c0 = 2 * (lane & 3);
#pragma unroll
                for (int mi = 0; mi < 2; mi++)
#pragma unroll
                    for (int ni = 0; ni < 4; ni++) {
                        int col = ni * 8 + c0;
                        float bb0 = bias_s[ch * 32 + col];
                        float bb1 = bias_s[ch * 32 + col + 1];
                        int rr = r0 + mi * 16;
                        hs[rr * 33 + col]           = acc[mi][ni][0] + bb0;
                        hs[rr * 33 + col + 1]       = acc[mi][ni][1] + bb1;
                        hs[(rr + 8) * 33 + col]     = acc[mi][ni][2] + bb0;
                        hs[(rr + 8) * 33 + col + 1] = acc[mi][ni][3] + bb1;
                    }
            }
            __syncthreads();

            // sorted-run segmented reduce: 8 groups x 8 rows, 32 cols
            const int col  = t & 31;
            const int g    = t >> 5;
            const int colG = nbase + ch * 32 + col;
            const int r0   = g * 8;
            const bool countLane = (nhalf == 0) && (ch == 0) && (col == 0);

            int   cur = seg_s[r0];
            float s   = 0.0f;
            float mx  = NEG_INF;
            int   run = 0;
#pragma unroll
            for (int rr = 0; rr < 8; rr++) {
                int   sg = seg_s[r0 + rr];
                float v  = hs[(r0 + rr) * 33 + col];
                if (sg != cur) {
                    atomicAdd(&g_seg_sum[cur * DIM + colG], s);
                    atomicMax(&g_seg_max[cur * DIM + colG], enc_f(mx));
                    if (countLane) atomicAdd(&g_counts[cur], run);
                    cur = sg; s = 0.0f; mx = NEG_INF; run = 0;
                }
                s += v;
                mx = fmaxf(mx, v);
                run++;
            }
            atomicAdd(&g_seg_sum[cur * DIM + colG], s);
            atomicMax(&g_seg_max[cur * DIM + colG], enc_f(mx));
            if (countLane) atomicAdd(&g_counts[cur], run);
        }
    }
}

// ---------------- proj: HMMA fp16 GEMM + fused MLP-4 scatter ------------------
// 128 CTAs x 256 thr; tile M=64 segs, N=256 cols, K=512 in 8 chunks of 64.
// 8 warps (2M x 4N), warp tile 32x64.
__global__ void __launch_bounds__(256, 1) proj_scatter(
    const int*   __restrict__ bidx,
    const float* __restrict__ bp,
    float4*      __restrict__ out4)
{
    extern __shared__ char smem[];
    const uint32_t sb = smem_u32(smem);
    const int t    = threadIdx.x;
    const int w    = t >> 5;
    const int lane = t & 31;
    const int wm   = w >> 2;         // 0..1
    const int wn   = w & 3;          // 0..3
    const int tileM = blockIdx.x * 64;

    int*   cnt_s  = (int*)(smem + P_OFF_CNT);
    float* invc_s = (float*)(smem + P_OFF_INV);
    float* bp_s   = (float*)(smem + P_OFF_BP);
    float* outs   = (float*)(smem + P_OFF_OUT);

    if (t < 64) {
        int cn = g_counts[tileM + t];
        cnt_s[t]  = cn;
        invc_s[t] = 1.0f / (float)max(cn, 1);
    }
    bp_s[t] = bp[t];   // 256 threads cover all 256 bias values

    const uint32_t xmask  = RSWZ(lane);
    const uint32_t a_base = sb + P_OFF_XA + (uint32_t)(wm * 32 + (lane & 15)) * 128u + (uint32_t)(lane >> 4) * 16u;
    const uint32_t b_base = sb + P_OFF_B  + (uint32_t)(wn * 64 + (lane & 15)) * 128u + (uint32_t)(lane >> 4) * 16u;

    float acc[2][8][4];
#pragma unroll
    for (int mi = 0; mi < 2; mi++)
#pragma unroll
        for (int ni = 0; ni < 8; ni++)
#pragma unroll
            for (int d = 0; d < 4; d++) acc[mi][ni][d] = 0.0f;

#pragma unroll 1
    for (int kc = 0; kc < 8; kc++) {
        __syncthreads();

        // xpool chunk: 64 rows x 64 k -> fp16 swizzled. 1024 float4 / 256 thr
#pragma unroll
        for (int i = 0; i < 4; i++) {
            int idx = i * 256 + t;
            int row = idx >> 4, q = idx & 15;
            float4 va;
            if (kc < 4) {
                va = *(const float4*)&g_seg_sum[(size_t)(tileM + row) * DIM + kc * 64 + q * 4];
                float iv = invc_s[row];
                va.x *= iv; va.y *= iv; va.z *= iv; va.w *= iv;
            } else {
                uint4 u = *(const uint4*)&g_seg_max[(size_t)(tileM + row) * DIM + (kc - 4) * 64 + q * 4];
                if (cnt_s[row] > 0) {
                    va.x = dec_f(u.x); va.y = dec_f(u.y); va.z = dec_f(u.z); va.w = dec_f(u.w);
                } else {
                    va.x = va.y = va.z = va.w = 0.0f;
                }
            }
            __half2 h0 = __floats2half2_rn(va.x, va.y);
            __half2 h1 = __floats2half2_rn(va.z, va.w);
            uint32_t addr = (sb + P_OFF_XA + (uint32_t)row * 128u + (uint32_t)q * 8u) ^ RSWZ(row);
            sts8(addr, *(uint32_t*)&h0, *(uint32_t*)&h1);
        }
        // Wp chunk: 256 rows x 64 k fp16. 2048 uint4 / 256 thr
#pragma unroll
        for (int i = 0; i < 8; i++) {
            int idx = i * 256 + t;
            int row = idx >> 3, q = idx & 7;
            uint4 v = ((const uint4*)g_Wph)[row * 64 + kc * 8 + q];
            uint32_t addr = (sb + P_OFF_B + (uint32_t)row * 128u + (uint32_t)q * 16u) ^ RSWZ(row);
            sts16(addr, v);
        }
        __syncthreads();

#pragma unroll
        for (int ks = 0; ks < 4; ks++) {
            const uint32_t koff = (uint32_t)ks * 32u;
            uint32_t a0[4], a1[4];
            ldmat_x4(a0, (a_base + koff) ^ xmask);
            ldmat_x4(a1, (a_base + 16u * 128u + koff) ^ xmask);
#pragma unroll
            for (int p = 0; p < 4; p++) {
                uint32_t bf[4];
                ldmat_x4(bf, (b_base + (uint32_t)p * 2048u + koff) ^ xmask);
                mma16816(acc[0][2 * p],     a0, bf[0], bf[2]);
                mma16816(acc[0][2 * p + 1], a0, bf[1], bf[3]);
                mma16816(acc[1][2 * p],     a1, bf[0], bf[2]);
                mma16816(acc[1][2 * p + 1], a1, bf[1], bf[3]);
            }
        }
    }

    // ---- stage out tile [64 x 256] fp32 (+bias) ----
    {
        const int r0 = wm * 32 + (lane >> 2);
        const int c0 = wn * 64 + 2 * (lane & 3);
#pragma unroll
        for (int mi = 0; mi < 2; mi++)
#pragma unroll
            for (int ni = 0; ni < 8; ni++) {
                int col = c0 + ni * 8;
                float bb0 = bp_s[col], bb1 = bp_s[col + 1];
                int rr = r0 + mi * 16;
                outs[rr * OUT_LD + col]           = acc[mi][ni][0] + bb0;
                outs[rr * OUT_LD + col + 1]       = acc[mi][ni][1] + bb1;
                outs[(rr + 8) * OUT_LD + col]     = acc[mi][ni][2] + bb0;
                outs[(rr + 8) * OUT_LD + col + 1] = acc[mi][ni][3] + bb1;
            }
    }
    __syncthreads();

    // ---- scatter rows [rowstart(tileM), rowstart(tileM+64)) with MLP=4 ----
    const int rstart = g_rowstart[tileM];
    const int rend   = g_rowstart[tileM + 64];
    const int cq     = t & 63;           // float4 column
    int r = rstart + (t >> 6);           // 4 row-lanes, stride 4
    for (; r + 12 < rend; r += 16) {
        int s0 = __ldg(&bidx[r])      - tileM;
        int s1 = __ldg(&bidx[r +  4]) - tileM;
        int s2 = __ldg(&bidx[r +  8]) - tileM;
        int s3 = __ldg(&bidx[r + 12]) - tileM;
        float4 v0 = *(const float4*)&outs[s0 * OUT_LD + cq * 4];
        float4 v1 = *(const float4*)&outs[s1 * OUT_LD + cq * 4];
        float4 v2 = *(const float4*)&outs[s2 * OUT_LD + cq * 4];
        float4 v3 = *(const float4*)&outs[s3 * OUT_LD + cq * 4];
        out4[(size_t)r * 64 + cq]        = v0;
        out4[(size_t)(r +  4) * 64 + cq] = v1;
        out4[(size_t)(r +  8) * 64 + cq] = v2;
        out4[(size_t)(r + 12) * 64 + cq] = v3;
    }
    for (; r < rend; r += 4) {
        int s0 = __ldg(&bidx[r]) - tileM;
        out4[(size_t)r * 64 + cq] = *(const float4*)&outs[s0 * OUT_LD + cq * 4];
    }
}

// ---------------- launch -----------------------------------------------------
extern "C" void kernel_launch(void* const* d_in, const int* in_sizes, int n_in,
                              void* d_out, int out_size) {
    const float* x    = (const float*)d_in[0];
    const int*   bidx = (const int*)  d_in[1];
    const float* W1   = (const float*)d_in[2];
    const float* b1   = (const float*)d_in[3];
    const float* Wp   = (const float*)d_in[4];
    const float* bp   = (const float*)d_in[5];

    cudaFuncSetAttribute(gemm_pool_mma, cudaFuncAttributeMaxDynamicSharedMemorySize,
                         SMEM_A_BYTES);
    cudaFuncSetAttribute(proj_scatter, cudaFuncAttributeMaxDynamicSharedMemorySize,
                         SMEM_P_BYTES);

    init_kernel<<<(NSEG * DIM + 255) / 256, 256>>>();
    wconv_kernel<<<384, 256>>>(W1, Wp);
    rowstart_kernel<<<NSEG / 256, 256>>>(bidx);

    gemm_pool_mma<<<GRID_A, 256, SMEM_A_BYTES>>>(x, bidx, b1);

    proj_scatter<<<NSEG / 64, 256, SMEM_P_BYTES>>>(bidx, bp, (float4*)d_out);
}

// round 8
// speedup vs baseline: 1.2658x; 1.0718x over previous
#include <cuda_runtime.h>
#include <cuda_fp16.h>
#include <cstdint>

#define N_ROWS 524288
#define DIM 256
#define NSEG 8192
#define M_TILES 4096      // 128-row M tiles
#define GRID_A 148

// ---------------- scratch (device globals) ----------------------------------
__device__ float    g_seg_sum[NSEG * DIM];
__device__ unsigned g_seg_max[NSEG * DIM];
__device__ int      g_counts[NSEG];
__device__ int      g_rowstart[NSEG + 1];
__device__ __half   g_W1h[DIM * DIM];
__device__ __half   g_Wph[DIM * 2 * DIM];
__device__ __half   g_xh[(size_t)N_ROWS * DIM];   // 268 MB fp16 copy of x

// ---------------- helpers ----------------------------------------------------
__device__ __forceinline__ uint32_t smem_u32(const void* p) {
    uint32_t a;
    asm("{ .reg .u64 t; cvta.to.shared.u64 t, %1; cvt.u32.u64 %0, t; }" : "=r"(a) : "l"(p));
    return a;
}
__device__ __forceinline__ void ldmat_x4(uint32_t r[4], uint32_t addr) {
    asm volatile("ldmatrix.sync.aligned.m8n8.x4.shared.b16 {%0,%1,%2,%3}, [%4];"
                 : "=r"(r[0]), "=r"(r[1]), "=r"(r[2]), "=r"(r[3]) : "r"(addr));
}
__device__ __forceinline__ void mma16816(float d[4], const uint32_t a[4],
                                         uint32_t b0, uint32_t b1) {
    asm volatile("mma.sync.aligned.m16n8k16.row.col.f32.f16.f16.f32 "
                 "{%0,%1,%2,%3}, {%4,%5,%6,%7}, {%8,%9}, {%0,%1,%2,%3};"
                 : "+f"(d[0]), "+f"(d[1]), "+f"(d[2]), "+f"(d[3])
                 : "r"(a[0]), "r"(a[1]), "r"(a[2]), "r"(a[3]), "r"(b0), "r"(b1));
}
__device__ __forceinline__ void sts8(uint32_t addr, uint32_t u0, uint32_t u1) {
    asm volatile("st.shared.v2.b32 [%0], {%1,%2};" :: "r"(addr), "r"(u0), "r"(u1) : "memory");
}
__device__ __forceinline__ void sts16(uint32_t addr, uint4 v) {
    asm volatile("st.shared.v4.b32 [%0], {%1,%2,%3,%4};"
                 :: "r"(addr), "r"(v.x), "r"(v.y), "r"(v.z), "r"(v.w) : "memory");
}
__device__ __forceinline__ void cpasync16(uint32_t dst, const void* src) {
    asm volatile("cp.async.cg.shared.global [%0], [%1], 16;" :: "r"(dst), "l"(src) : "memory");
}
#define CP_COMMIT() asm volatile("cp.async.commit_group;" ::: "memory")
#define CP_WAIT0()  asm volatile("cp.async.wait_group 0;"  ::: "memory")

__device__ __forceinline__ unsigned enc_f(float f) {
    unsigned i = __float_as_uint(f);
    return (i & 0x80000000u) ? ~i : (i | 0x80000000u);
}
__device__ __forceinline__ float dec_f(unsigned u) {
    return __uint_as_float((u & 0x80000000u) ? (u & 0x7FFFFFFFu) : ~u);
}
#define RSWZ(row) (((uint32_t)((row) & 7)) << 4)

// ---------------- kernel A smem layout (512B rows, swizzled) ----------------
#define OFF_W    0u          // 256 rows x 512B = 131072
#define OFF_A    131072u     // 128 rows x 512B = 65536
#define OFF_HS   196608u     // 128 x 65 x 4 = 33280
#define OFF_BIAS 229888u     // 1024
#define OFF_SEG  230912u     // 512
#define SMEM_A_BYTES 231424

// ---------------- proj smem layout (tile M=32) --------------------------------
#define P_OFF_B    0u        // Wp chunk: 256 x 128B = 32768
#define P_OFF_XA   32768u    // xpool chunk: 32 x 128B = 4096
#define P_OFF_OUT  36864u    // 32 x 260 x 4 = 33280
#define P_OFF_CNT  70144u    // 128
#define P_OFF_INV  70272u    // 128
#define P_OFF_BP   70400u    // 1024
#define SMEM_P_BYTES 71424
#define OUT_LD 260

// ---------------- init -------------------------------------------------------
__global__ void init_kernel() {
    int i = blockIdx.x * blockDim.x + threadIdx.x;
    if (i < NSEG * DIM) {
        g_seg_sum[i] = 0.0f;
        g_seg_max[i] = 0u;
    }
    if (i < NSEG) g_counts[i] = 0;
}

// ---------------- weight conversion fp32 -> fp16 (W1 + Wp) -------------------
__global__ void wconv_kernel(const float* __restrict__ W1, const float* __restrict__ Wp) {
    int i = blockIdx.x * 256 + threadIdx.x;
    if (i < 32768) {
        float2 f = ((const float2*)W1)[i];
        ((__half2*)g_W1h)[i] = __floats2half2_rn(f.x, f.y);
    } else {
        int j = i - 32768;
        float2 f = ((const float2*)Wp)[j];
        ((__half2*)g_Wph)[j] = __floats2half2_rn(f.x, f.y);
    }
}

// ---------------- x conversion fp32 -> fp16 (268 MB) -------------------------
__global__ void xconv_kernel(const float* __restrict__ x) {
    const float4* x4 = (const float4*)x;
    uint2* o = (uint2*)g_xh;
    int base = blockIdx.x * 1024 + threadIdx.x;
#pragma unroll
    for (int i = 0; i < 4; i++) {
        float4 v = x4[base + i * 256];
        __half2 h0 = __floats2half2_rn(v.x, v.y);
        __half2 h1 = __floats2half2_rn(v.z, v.w);
        o[base + i * 256] = make_uint2(*(uint32_t*)&h0, *(uint32_t*)&h1);
    }
}

// ---------------- rowstart: lower_bound of each segment in sorted bidx -------
__global__ void rowstart_kernel(const int* __restrict__ bidx) {
    int s = blockIdx.x * 256 + threadIdx.x;
    int lo = 0, hi = N_ROWS;
    while (lo < hi) {
        int mid = (lo + hi) >> 1;
        if (__ldg(&bidx[mid]) < s) lo = mid + 1; else hi = mid;
    }
    g_rowstart[s] = lo;
    if (s == 0) g_rowstart[NSEG] = N_ROWS;
}

// ---------------- kernel A: HMMA GEMM + segmented sum/max --------------------
// 512 thr = 16 warps (4M x 4N); tile 128x256; x tile via cp.async fp16,
// prefetch of tile i+1 hidden behind epilogue of tile i.
__global__ void __launch_bounds__(512, 1) gemm_pool_mma(
    const int*   __restrict__ bidx,
    const float* __restrict__ b1)
{
    extern __shared__ char smem[];
    const uint32_t sb = smem_u32(smem);
    const int t    = threadIdx.x;
    const int w    = t >> 5;
    const int lane = t & 31;
    const int wm   = w >> 2;
    const int wn   = w & 3;

    float* bias_s = (float*)(smem + OFF_BIAS);
    int*   seg_s  = (int*)(smem + OFF_SEG);
    float* hs     = (float*)(smem + OFF_HS);

    // ---- issue cp.async for first tile immediately ----
    {
        const int rowbase = blockIdx.x * 128;
#pragma unroll
        for (int j = 0; j < 8; j++) {
            int idx = j * 512 + t;           // 4096 16B chunks
            int r = idx >> 5, q = idx & 31;
            uint32_t dst = (sb + OFF_A + (uint32_t)r * 512u + (uint32_t)q * 16u) ^ RSWZ(r);
            cpasync16(dst, g_xh + (size_t)(rowbase + r) * DIM + q * 8);
        }
        CP_COMMIT();
        if (t < 128) seg_s[t] = bidx[rowbase + t];
    }

    if (t < 256) bias_s[t] = b1[t];

    // ---- W1 fp16 -> SMEM [n][k] 512B rows, swizzled (once per CTA) ----
    {
        const uint4* wsrc = (const uint4*)g_W1h;   // 8192 uint4
#pragma unroll
        for (int j = 0; j < 16; j++) {
            int idx = j * 512 + t;
            int row = idx >> 5, q = idx & 31;
            uint32_t addr = (sb + OFF_W + (uint32_t)row * 512u + (uint32_t)q * 16u) ^ RSWZ(row);
            sts16(addr, wsrc[idx]);
        }
    }
    CP_WAIT0();
    __syncthreads();

    const uint32_t xmask  = RSWZ(lane);
    const uint32_t a_base = sb + OFF_A + (uint32_t)(wm * 32 + (lane & 15)) * 512u + (uint32_t)(lane >> 4) * 16u;
    const uint32_t b_base = sb + OFF_W + (uint32_t)(wn * 64 + (lane & 15)) * 512u + (uint32_t)(lane >> 4) * 16u;

    const float NEG_INF = __int_as_float(0xff800000);

    for (int tile = blockIdx.x; tile < M_TILES; tile += GRID_A) {
        // ---- HMMA mainloop: K = 256 in 16 steps ----
        float acc[2][8][4];
#pragma unroll
        for (int mi = 0; mi < 2; mi++)
#pragma unroll
            for (int ni = 0; ni < 8; ni++)
#pragma unroll
                for (int d = 0; d < 4; d++) acc[mi][ni][d] = 0.0f;

#pragma unroll 4
        for (int ks = 0; ks < 16; ks++) {
            const uint32_t koff = (uint32_t)ks * 32u;
            uint32_t a0[4], a1[4];
            ldmat_x4(a0, (a_base + koff) ^ xmask);
            ldmat_x4(a1, (a_base + 16u * 512u + koff) ^ xmask);
#pragma unroll
            for (int p = 0; p < 4; p++) {
                uint32_t bf[4];
                ldmat_x4(bf, (b_base + (uint32_t)p * 8192u + koff) ^ xmask);
                mma16816(acc[0][2 * p],     a0, bf[0], bf[2]);
                mma16816(acc[0][2 * p + 1], a0, bf[1], bf[3]);
                mma16816(acc[1][2 * p],     a1, bf[0], bf[2]);
                mma16816(acc[1][2 * p + 1], a1, bf[1], bf[3]);
            }
        }
        __syncthreads();   // all warps done reading A

        // ---- prefetch next x tile via cp.async (no registers held) ----
        const int  ntile = tile + GRID_A;
        const bool more  = ntile < M_TILES;
        int segnext = 0;
        if (more) {
            const int nrow = ntile * 128;
#pragma unroll
            for (int j = 0; j < 8; j++) {
                int idx = j * 512 + t;
                int r = idx >> 5, q = idx & 31;
                uint32_t dst = (sb + OFF_A + (uint32_t)r * 512u + (uint32_t)q * 16u) ^ RSWZ(r);
                cpasync16(dst, g_xh + (size_t)(nrow + r) * DIM + q * 8);
            }
            if (t < 128) segnext = bidx[nrow + t];
        }
        CP_COMMIT();

        // ---- epilogue: 4 N-chunks of 64 cols; stage in hs ----
#pragma unroll 1
        for (int ch = 0; ch < 4; ch++) {
            if (ch) __syncthreads();
            if (wn == ch) {
                const int r0 = wm * 32 + (lane >> 2);
                const int c0 = 2 * (lane & 3);
#pragma unroll
                for (int mi = 0; mi < 2; mi++)
#pragma unroll
                    for (int ni = 0; ni < 8; ni++) {
                        int col = ni * 8 + c0;
                        float bb0 = bias_s[ch * 64 + col];
                        float bb1 = bias_s[ch * 64 + col + 1];
                        int rr = r0 + mi * 16;
                        hs[rr * 65 + col]           = acc[mi][ni][0] + bb0;
                        hs[rr * 65 + col + 1]       = acc[mi][ni][1] + bb1;
                        hs[(rr + 8) * 65 + col]     = acc[mi][ni][2] + bb0;
                        hs[(rr + 8) * 65 + col + 1] = acc[mi][ni][3] + bb1;
                    }
            }
            __syncthreads();

            // sorted-run segmented reduce: 8 groups x 16 rows, 64 cols
            const int col  = t & 63;
            const int g    = t >> 6;
            const int colG = ch * 64 + col;
            const int r0   = g * 16;
            const bool countLane = (ch == 0) && (col == 0);

            int   cur = seg_s[r0];
            float s   = 0.0f;
            float mx  = NEG_INF;
            int   run = 0;
#pragma unroll 4
            for (int rr = 0; rr < 16; rr++) {
                int   sg = seg_s[r0 + rr];
                float v  = hs[(r0 + rr) * 65 + col];
                if (sg != cur) {
                    atomicAdd(&g_seg_sum[cur * DIM + colG], s);
                    atomicMax(&g_seg_max[cur * DIM + colG], enc_f(mx));
                    if (countLane) atomicAdd(&g_counts[cur], run);
                    cur = sg; s = 0.0f; mx = NEG_INF; run = 0;
                }
                s += v;
                mx = fmaxf(mx, v);
                run++;
            }
            atomicAdd(&g_seg_sum[cur * DIM + colG], s);
            atomicMax(&g_seg_max[cur * DIM + colG], enc_f(mx));
            if (countLane) atomicAdd(&g_counts[cur], run);
        }

        CP_WAIT0();
        __syncthreads();   // A(next) visible; everyone done with hs/seg_s
        if (more && t < 128) seg_s[t] = segnext;   // ordered before next epi by post-ML sync
    }
}

// ---------------- proj: HMMA fp16 GEMM + fused MLP-4 scatter ------------------
// 256 CTAs x 256 thr (2/SM); tile M=32 segs, N=256 cols, K=512 in 8 chunks.
// 8 warps, warp tile 32(M) x 32(N).
__global__ void __launch_bounds__(256, 2) proj_scatter(
    const int*   __restrict__ bidx,
    const float* __restrict__ bp,
    float4*      __restrict__ out4)
{
    extern __shared__ char smem[];
    const uint32_t sb = smem_u32(smem);
    const int t    = threadIdx.x;
    const int w    = t >> 5;
    const int lane = t & 31;
    const int wn   = w;              // 0..7, 32-col band
    const int tileM = blockIdx.x * 32;

    int*   cnt_s  = (int*)(smem + P_OFF_CNT);
    float* invc_s = (float*)(smem + P_OFF_INV);
    float* bp_s   = (float*)(smem + P_OFF_BP);
    float* outs   = (float*)(smem + P_OFF_OUT);

    if (t < 32) {
        int cn = g_counts[tileM + t];
        cnt_s[t]  = cn;
        invc_s[t] = 1.0f / (float)max(cn, 1);
    }
    bp_s[t] = bp[t];   // 256 threads cover 256 biases

    const uint32_t xmask  = RSWZ(lane);
    const uint32_t a_base = sb + P_OFF_XA + (uint32_t)(lane & 15) * 128u + (uint32_t)(lane >> 4) * 16u;
    const uint32_t b_base = sb + P_OFF_B  + (uint32_t)(wn * 32 + (lane & 15)) * 128u + (uint32_t)(lane >> 4) * 16u;

    float acc[2][4][4];
#pragma unroll
    for (int mi = 0; mi < 2; mi++)
#pragma unroll
        for (int ni = 0; ni < 4; ni++)
#pragma unroll
            for (int d = 0; d < 4; d++) acc[mi][ni][d] = 0.0f;

#pragma unroll 1
    for (int kc = 0; kc < 8; kc++) {
        __syncthreads();

        // xpool chunk: 32 rows x 64 k -> fp16 swizzled. 512 float4 / 256 thr
#pragma unroll
        for (int i = 0; i < 2; i++) {
            int idx = i * 256 + t;
            int row = idx >> 4, q = idx & 15;
            float4 va;
            if (kc < 4) {
                va = *(const float4*)&g_seg_sum[(size_t)(tileM + row) * DIM + kc * 64 + q * 4];
                float iv = invc_s[row];
                va.x *= iv; va.y *= iv; va.z *= iv; va.w *= iv;
            } else {
                uint4 u = *(const uint4*)&g_seg_max[(size_t)(tileM + row) * DIM + (kc - 4) * 64 + q * 4];
                if (cnt_s[row] > 0) {
                    va.x = dec_f(u.x); va.y = dec_f(u.y); va.z = dec_f(u.z); va.w = dec_f(u.w);
                } else {
                    va.x = va.y = va.z = va.w = 0.0f;
                }
            }
            __half2 h0 = __floats2half2_rn(va.x, va.y);
            __half2 h1 = __floats2half2_rn(va.z, va.w);
            uint32_t addr = (sb + P_OFF_XA + (uint32_t)row * 128u + (uint32_t)q * 8u) ^ RSWZ(row);
            sts8(addr, *(uint32_t*)&h0, *(uint32_t*)&h1);
        }
        // Wp chunk: 256 rows x 64 k fp16. 2048 uint4 / 256 thr
#pragma unroll
        for (int i = 0; i < 8; i++) {
            int idx = i * 256 + t;
            int row = idx >> 3, q = idx & 7;
            uint4 v = ((const uint4*)g_Wph)[row * 64 + kc * 8 + q];
            uint32_t addr = (sb + P_OFF_B + (uint32_t)row * 128u + (uint32_t)q * 16u) ^ RSWZ(row);
            sts16(addr, v);
        }
        __syncthreads();

#pragma unroll
        for (int ks = 0; ks < 4; ks++) {
            const uint32_t koff = (uint32_t)ks * 32u;
            uint32_t a0[4], a1[4];
            ldmat_x4(a0, (a_base + koff) ^ xmask);
            ldmat_x4(a1, (a_base + 16u * 128u + koff) ^ xmask);
#pragma unroll
            for (int p = 0; p < 2; p++) {
                uint32_t bf[4];
                ldmat_x4(bf, (b_base + (uint32_t)p * 2048u + koff) ^ xmask);
                mma16816(acc[0][2 * p],     a0, bf[0], bf[2]);
                mma16816(acc[0][2 * p + 1], a0, bf[1], bf[3]);
                mma16816(acc[1][2 * p],     a1, bf[0], bf[2]);
                mma16816(acc[1][2 * p + 1], a1, bf[1], bf[3]);
            }
        }
    }

    // ---- stage out tile [32 x 256] fp32 (+bias) ----
    {
        const int r0 = lane >> 2;
        const int c0 = wn * 32 + 2 * (lane & 3);
#pragma unroll
        for (int mi = 0; mi < 2; mi++)
#pragma unroll
            for (int ni = 0; ni < 4; ni++) {
                int col = c0 + ni * 8;
                float bb0 = bp_s[col], bb1 = bp_s[col + 1];
                int rr = r0 + mi * 16;
                outs[rr * OUT_LD + col]           = acc[mi][ni][0] + bb0;
                outs[rr * OUT_LD + col + 1]       = acc[mi][ni][1] + bb1;
                outs[(rr + 8) * OUT_LD + col]     = acc[mi][ni][2] + bb0;
                outs[(rr + 8) * OUT_LD + col + 1] = acc[mi][ni][3] + bb1;
            }
    }
    __syncthreads();

    // ---- scatter rows [rowstart(tileM), rowstart(tileM+32)) with MLP=4 ----
    const int rstart = g_rowstart[tileM];
    const int rend   = g_rowstart[tileM + 32];
    const int cq     = t & 63;           // float4 column
    int r = rstart + (t >> 6);           // 4 row-lanes, stride 4
    for (; r + 12 < rend; r += 16) {
        int s0 = __ldg(&bidx[r])      - tileM;
        int s1 = __ldg(&bidx[r +  4]) - tileM;
        int s2 = __ldg(&bidx[r +  8]) - tileM;
        int s3 = __ldg(&bidx[r + 12]) - tileM;
        float4 v0 = *(const float4*)&outs[s0 * OUT_LD + cq * 4];
        float4 v1 = *(const float4*)&outs[s1 * OUT_LD + cq * 4];
        float4 v2 = *(const float4*)&outs[s2 * OUT_LD + cq * 4];
        float4 v3 = *(const float4*)&outs[s3 * OUT_LD + cq * 4];
        out4[(size_t)r * 64 + cq]        = v0;
        out4[(size_t)(r +  4) * 64 + cq] = v1;
        out4[(size_t)(r +  8) * 64 + cq] = v2;
        out4[(size_t)(r + 12) * 64 + cq] = v3;
    }
    for (; r < rend; r += 4) {
        int s0 = __ldg(&bidx[r]) - tileM;
        out4[(size_t)r * 64 + cq] = *(const float4*)&outs[s0 * OUT_LD + cq * 4];
    }
}

// ---------------- launch -----------------------------------------------------
extern "C" void kernel_launch(void* const* d_in, const int* in_sizes, int n_in,
                              void* d_out, int out_size) {
    const float* x    = (const float*)d_in[0];
    const int*   bidx = (const int*)  d_in[1];
    const float* W1   = (const float*)d_in[2];
    const float* b1   = (const float*)d_in[3];
    const float* Wp   = (const float*)d_in[4];
    const float* bp   = (const float*)d_in[5];

    cudaFuncSetAttribute(gemm_pool_mma, cudaFuncAttributeMaxDynamicSharedMemorySize,
                         SMEM_A_BYTES);
    cudaFuncSetAttribute(proj_scatter, cudaFuncAttributeMaxDynamicSharedMemorySize,
                         SMEM_P_BYTES);

    init_kernel<<<(NSEG * DIM + 255) / 256, 256>>>();
    wconv_kernel<<<384, 256>>>(W1, Wp);
    rowstart_kernel<<<NSEG / 256, 256>>>(bidx);
    xconv_kernel<<<32768, 256>>>(x);

    gemm_pool_mma<<<GRID_A, 512, SMEM_A_BYTES>>>(bidx, b1);

    proj_scatter<<<NSEG / 32, 256, SMEM_P_BYTES>>>(bidx, bp, (float4*)d_out);
}

// round 9
// speedup vs baseline: 1.4316x; 1.1309x over previous
#include <cuda_runtime.h>
#include <cuda_fp16.h>
#include <cstdint>

#define N_ROWS 524288
#define DIM 256
#define NSEG 8192
#define M_TILES 4096      // 128-row M tiles
#define GRID_A 148

// ---------------- scratch (device globals) ----------------------------------
__device__ float    g_seg_sum[NSEG * DIM];
__device__ unsigned g_seg_max[NSEG * DIM];
__device__ int      g_rowstart[NSEG + 1];
__device__ __half   g_W1h[DIM * DIM];
__device__ __half   g_Wph[DIM * 2 * DIM];
__device__ __half   g_xh[(size_t)N_ROWS * DIM];   // 268 MB fp16 copy of x

// ---------------- helpers ----------------------------------------------------
__device__ __forceinline__ uint32_t smem_u32(const void* p) {
    uint32_t a;
    asm("{ .reg .u64 t; cvta.to.shared.u64 t, %1; cvt.u32.u64 %0, t; }" : "=r"(a) : "l"(p));
    return a;
}
__device__ __forceinline__ void ldmat_x4(uint32_t r[4], uint32_t addr) {
    asm volatile("ldmatrix.sync.aligned.m8n8.x4.shared.b16 {%0,%1,%2,%3}, [%4];"
                 : "=r"(r[0]), "=r"(r[1]), "=r"(r[2]), "=r"(r[3]) : "r"(addr));
}
__device__ __forceinline__ void mma16816(float d[4], const uint32_t a[4],
                                         uint32_t b0, uint32_t b1) {
    asm volatile("mma.sync.aligned.m16n8k16.row.col.f32.f16.f16.f32 "
                 "{%0,%1,%2,%3}, {%4,%5,%6,%7}, {%8,%9}, {%0,%1,%2,%3};"
                 : "+f"(d[0]), "+f"(d[1]), "+f"(d[2]), "+f"(d[3])
                 : "r"(a[0]), "r"(a[1]), "r"(a[2]), "r"(a[3]), "r"(b0), "r"(b1));
}
__device__ __forceinline__ void sts8(uint32_t addr, uint32_t u0, uint32_t u1) {
    asm volatile("st.shared.v2.b32 [%0], {%1,%2};" :: "r"(addr), "r"(u0), "r"(u1) : "memory");
}
__device__ __forceinline__ void sts16(uint32_t addr, uint4 v) {
    asm volatile("st.shared.v4.b32 [%0], {%1,%2,%3,%4};"
                 :: "r"(addr), "r"(v.x), "r"(v.y), "r"(v.z), "r"(v.w) : "memory");
}
__device__ __forceinline__ void cpasync16(uint32_t dst, const void* src) {
    asm volatile("cp.async.cg.shared.global [%0], [%1], 16;" :: "r"(dst), "l"(src) : "memory");
}
#define CP_COMMIT() asm volatile("cp.async.commit_group;" ::: "memory")
#define CP_WAIT0()  asm volatile("cp.async.wait_group 0;"  ::: "memory")

__device__ __forceinline__ unsigned enc_f(float f) {
    unsigned i = __float_as_uint(f);
    return (i & 0x80000000u) ? ~i : (i | 0x80000000u);
}
__device__ __forceinline__ float dec_f(unsigned u) {
    return __uint_as_float((u & 0x80000000u) ? (u & 0x7FFFFFFFu) : ~u);
}
#define RSWZ(row) (((uint32_t)((row) & 7)) << 4)

// ---------------- kernel A smem layout (512B rows, swizzled) ----------------
#define OFF_W    0u          // 256 rows x 512B = 131072
#define OFF_A    131072u     // 128 rows x 512B = 65536
#define OFF_BIAS 196608u     // 1024
#define OFF_SEG  197632u     // 512
#define SMEM_A_BYTES 198144

// ---------------- proj smem layout (tile M=32) --------------------------------
#define P_OFF_B    0u        // Wp chunk: 256 x 128B = 32768
#define P_OFF_XA   32768u    // xpool chunk: 32 x 128B = 4096
#define P_OFF_OUT  36864u    // 32 x 260 x 4 = 33280
#define P_OFF_CNT  70144u    // 128
#define P_OFF_INV  70272u    // 128
#define P_OFF_BP   70400u    // 1024
#define SMEM_P_BYTES 71424
#define OUT_LD 260

// ---------------- init -------------------------------------------------------
__global__ void init_kernel() {
    int i = blockIdx.x * blockDim.x + threadIdx.x;
    g_seg_sum[i] = 0.0f;
    g_seg_max[i] = 0u;
}

// ---------------- weight conversion fp32 -> fp16 (W1 + Wp) -------------------
__global__ void wconv_kernel(const float* __restrict__ W1, const float* __restrict__ Wp) {
    int i = blockIdx.x * 256 + threadIdx.x;
    if (i < 32768) {
        float2 f = ((const float2*)W1)[i];
        ((__half2*)g_W1h)[i] = __floats2half2_rn(f.x, f.y);
    } else {
        int j = i - 32768;
        float2 f = ((const float2*)Wp)[j];
        ((__half2*)g_Wph)[j] = __floats2half2_rn(f.x, f.y);
    }
}

// ---------------- x conversion fp32 -> fp16 (268 MB) -------------------------
__global__ void xconv_kernel(const float* __restrict__ x) {
    const float4* x4 = (const float4*)x;
    uint2* o = (uint2*)g_xh;
    int base = blockIdx.x * 1024 + threadIdx.x;
#pragma unroll
    for (int i = 0; i < 4; i++) {
        float4 v = x4[base + i * 256];
        __half2 h0 = __floats2half2_rn(v.x, v.y);
        __half2 h1 = __floats2half2_rn(v.z, v.w);
        o[base + i * 256] = make_uint2(*(uint32_t*)&h0, *(uint32_t*)&h1);
    }
}

// ---------------- rowstart: lower_bound of each segment in sorted bidx -------
__global__ void rowstart_kernel(const int* __restrict__ bidx) {
    int s = blockIdx.x * 256 + threadIdx.x;
    int lo = 0, hi = N_ROWS;
    while (lo < hi) {
        int mid = (lo + hi) >> 1;
        if (__ldg(&bidx[mid]) < s) lo = mid + 1; else hi = mid;
    }
    g_rowstart[s] = lo;
    if (s == 0) g_rowstart[NSEG] = N_ROWS;
}

// ---------------- kernel A: HMMA GEMM + shuffle segmented reduce -------------
// 512 thr = 16 warps (4M x 4N); tile 128x256; cp.async fp16 prefetch;
// barrier-free register epilogue.
__global__ void __launch_bounds__(512, 1) gemm_pool_mma(
    const int*   __restrict__ bidx,
    const float* __restrict__ b1)
{
    extern __shared__ char smem[];
    const uint32_t sb = smem_u32(smem);
    const int t    = threadIdx.x;
    const int w    = t >> 5;
    const int lane = t & 31;
    const int wm   = w >> 2;
    const int wn   = w & 3;

    float* bias_s = (float*)(smem + OFF_BIAS);
    int*   seg_s  = (int*)(smem + OFF_SEG);

    // ---- issue cp.async for first tile immediately ----
    {
        const int rowbase = blockIdx.x * 128;
#pragma unroll
        for (int j = 0; j < 8; j++) {
            int idx = j * 512 + t;           // 4096 16B chunks
            int r = idx >> 5, q = idx & 31;
            uint32_t dst = (sb + OFF_A + (uint32_t)r * 512u + (uint32_t)q * 16u) ^ RSWZ(r);
            cpasync16(dst, g_xh + (size_t)(rowbase + r) * DIM + q * 8);
        }
        CP_COMMIT();
        if (t < 128) seg_s[t] = bidx[rowbase + t];
    }

    if (t < 256) bias_s[t] = b1[t];

    // ---- W1 fp16 -> SMEM [n][k] 512B rows, swizzled (once per CTA) ----
    {
        const uint4* wsrc = (const uint4*)g_W1h;   // 8192 uint4
#pragma unroll
        for (int j = 0; j < 16; j++) {
            int idx = j * 512 + t;
            int row = idx >> 5, q = idx & 31;
            uint32_t addr = (sb + OFF_W + (uint32_t)row * 512u + (uint32_t)q * 16u) ^ RSWZ(row);
            sts16(addr, wsrc[idx]);
        }
    }
    CP_WAIT0();
    __syncthreads();

    const uint32_t xmask  = RSWZ(lane);
    const uint32_t a_base = sb + OFF_A + (uint32_t)(wm * 32 + (lane & 15)) * 512u + (uint32_t)(lane >> 4) * 16u;
    const uint32_t b_base = sb + OFF_W + (uint32_t)(wn * 64 + (lane & 15)) * 512u + (uint32_t)(lane >> 4) * 16u;

    // bias for this thread's 16 columns (col = wn*64 + ni*8 + 2*(lane&3) + p)
    const int colbase = wn * 64 + 2 * (lane & 3);
    float bb[16];
#pragma unroll
    for (int i = 0; i < 16; i++) bb[i] = bias_s[colbase + (i >> 1) * 8 + (i & 1)];

    for (int tile = blockIdx.x; tile < M_TILES; tile += GRID_A) {
        // ---- HMMA mainloop: K = 256 in 16 steps ----
        float acc[2][8][4];
#pragma unroll
        for (int mi = 0; mi < 2; mi++)
#pragma unroll
            for (int ni = 0; ni < 8; ni++)
#pragma unroll
                for (int d = 0; d < 4; d++) acc[mi][ni][d] = 0.0f;

#pragma unroll 4
        for (int ks = 0; ks < 16; ks++) {
            const uint32_t koff = (uint32_t)ks * 32u;
            uint32_t a0[4], a1[4];
            ldmat_x4(a0, (a_base + koff) ^ xmask);
            ldmat_x4(a1, (a_base + 16u * 512u + koff) ^ xmask);
#pragma unroll
            for (int p = 0; p < 4; p++) {
                uint32_t bf[4];
                ldmat_x4(bf, (b_base + (uint32_t)p * 8192u + koff) ^ xmask);
                mma16816(acc[0][2 * p],     a0, bf[0], bf[2]);
                mma16816(acc[0][2 * p + 1], a0, bf[1], bf[3]);
                mma16816(acc[1][2 * p],     a1, bf[0], bf[2]);
                mma16816(acc[1][2 * p + 1], a1, bf[1], bf[3]);
            }
        }
        __syncthreads();   // all warps done reading A

        // ---- prefetch next x tile via cp.async ----
        const int  ntile = tile + GRID_A;
        const bool more  = ntile < M_TILES;
        int segnext = 0;
        if (more) {
            const int nrow = ntile * 128;
#pragma unroll
            for (int j = 0; j < 8; j++) {
                int idx = j * 512 + t;
                int r = idx >> 5, q = idx & 31;
                uint32_t dst = (sb + OFF_A + (uint32_t)r * 512u + (uint32_t)q * 16u) ^ RSWZ(r);
                cpasync16(dst, g_xh + (size_t)(nrow + r) * DIM + q * 8);
            }
            if (t < 128) segnext = bidx[nrow + t];
        }
        CP_COMMIT();

        // ---- barrier-free epilogue: bias + shuffle segmented reduce ----
        {
            // add bias into acc
#pragma unroll
            for (int mi = 0; mi < 2; mi++)
#pragma unroll
                for (int ni = 0; ni < 8; ni++)
#pragma unroll
                    for (int d = 0; d < 4; d++)
                        acc[mi][ni][d] += bb[ni * 2 + (d & 1)];

            float ps[16], pm[16];
            int pseg = -1;

#pragma unroll
            for (int b = 0; b < 4; b++) {
                const int mi = b >> 1, rh = b & 1;
                const int rb = wm * 32 + mi * 16 + rh * 8;
                const int seg0 = seg_s[rb];
                const int seg7 = seg_s[rb + 7];

                float v[16];
#pragma unroll
                for (int ni = 0; ni < 8; ni++) {
                    v[ni * 2]     = acc[mi][ni][2 * rh];
                    v[ni * 2 + 1] = acc[mi][ni][2 * rh + 1];
                }

                if (seg0 == seg7) {
                    // pure block (warp-uniform branch)
                    if (pseg == seg0) {
#pragma unroll
                        for (int i = 0; i < 16; i++) {
                            ps[i] += v[i];
                            pm[i] = fmaxf(pm[i], v[i]);
                        }
                    } else {
                        if (pseg >= 0) {
#pragma unroll
                            for (int r = 4; r <= 16; r <<= 1)
#pragma unroll
                                for (int i = 0; i < 16; i++) {
                                    ps[i] += __shfl_xor_sync(0xFFFFFFFFu, ps[i], r);
                                    pm[i] = fmaxf(pm[i], __shfl_xor_sync(0xFFFFFFFFu, pm[i], r));
                                }
                            unsigned gb = (unsigned)pseg * DIM + colbase;
                            if (lane < 4) {
#pragma unroll
                                for (int i = 0; i < 16; i++)
                                    atomicAdd(&g_seg_sum[gb + (i >> 1) * 8 + (i & 1)], ps[i]);
                            } else if (lane < 8) {
#pragma unroll
                                for (int i = 0; i < 16; i++)
                                    atomicMax(&g_seg_max[gb + (i >> 1) * 8 + (i & 1)], enc_f(pm[i]));
                            }
                        }
#pragma unroll
                        for (int i = 0; i < 16; i++) { ps[i] = v[i]; pm[i] = v[i]; }
                        pseg = seg0;
                    }
                } else {
                    // impure block: one row per thread, direct atomics
                    const int myseg = seg_s[rb + (lane >> 2)];
                    unsigned gb = (unsigned)myseg * DIM + colbase;
#pragma unroll
                    for (int i = 0; i < 16; i++) {
                        atomicAdd(&g_seg_sum[gb + (i >> 1) * 8 + (i & 1)], v[i]);
                        atomicMax(&g_seg_max[gb + (i >> 1) * 8 + (i & 1)], enc_f(v[i]));
                    }
                }
            }
            if (pseg >= 0) {
#pragma unroll
                for (int r = 4; r <= 16; r <<= 1)
#pragma unroll
                    for (int i = 0; i < 16; i++) {
                        ps[i] += __shfl_xor_sync(0xFFFFFFFFu, ps[i], r);
                        pm[i] = fmaxf(pm[i], __shfl_xor_sync(0xFFFFFFFFu, pm[i], r));
                    }
                unsigned gb = (unsigned)pseg * DIM + colbase;
                if (lane < 4) {
#pragma unroll
                    for (int i = 0; i < 16; i++)
                        atomicAdd(&g_seg_sum[gb + (i >> 1) * 8 + (i & 1)], ps[i]);
                } else if (lane < 8) {
#pragma unroll
                    for (int i = 0; i < 16; i++)
                        atomicMax(&g_seg_max[gb + (i >> 1) * 8 + (i & 1)], enc_f(pm[i]));
                }
            }
        }

        CP_WAIT0();
        __syncthreads();   // A(next) ready; all seg_s reads done
        if (more && t < 128) seg_s[t] = segnext;  // ordered before next epilogue by next post-mainloop sync
    }
}

// ---------------- proj: HMMA fp16 GEMM + fused MLP-4 scatter ------------------
// 256 CTAs x 256 thr (2/SM); tile M=32 segs, N=256 cols, K=512 in 8 chunks.
__global__ void __launch_bounds__(256, 2) proj_scatter(
    const int*   __restrict__ bidx,
    const float* __restrict__ bp,
    float4*      __restrict__ out4)
{
    extern __shared__ char smem[];
    const uint32_t sb = smem_u32(smem);
    const int t    = threadIdx.x;
    const int w    = t >> 5;
    const int lane = t & 31;
    const int wn   = w;              // 0..7, 32-col band
    const int tileM = blockIdx.x * 32;

    int*   cnt_s  = (int*)(smem + P_OFF_CNT);
    float* invc_s = (float*)(smem + P_OFF_INV);
    float* bp_s   = (float*)(smem + P_OFF_BP);
    float* outs   = (float*)(smem + P_OFF_OUT);

    if (t < 32) {
        int cn = g_rowstart[tileM + t + 1] - g_rowstart[tileM + t];
        cnt_s[t]  = cn;
        invc_s[t] = 1.0f / (float)max(cn, 1);
    }
    bp_s[t] = bp[t];

    const uint32_t xmask  = RSWZ(lane);
    const uint32_t a_base = sb + P_OFF_XA + (uint32_t)(lane & 15) * 128u + (uint32_t)(lane >> 4) * 16u;
    const uint32_t b_base = sb + P_OFF_B  + (uint32_t)(wn * 32 + (lane & 15)) * 128u + (uint32_t)(lane >> 4) * 16u;

    float acc[2][4][4];
#pragma unroll
    for (int mi = 0; mi < 2; mi++)
#pragma unroll
        for (int ni = 0; ni < 4; ni++)
#pragma unroll
            for (int d = 0; d < 4; d++) acc[mi][ni][d] = 0.0f;

#pragma unroll 1
    for (int kc = 0; kc < 8; kc++) {
        __syncthreads();

        // xpool chunk: 32 rows x 64 k -> fp16 swizzled
#pragma unroll
        for (int i = 0; i < 2; i++) {
            int idx = i * 256 + t;
            int row = idx >> 4, q = idx & 15;
            float4 va;
            if (kc < 4) {
                va = *(const float4*)&g_seg_sum[(size_t)(tileM + row) * DIM + kc * 64 + q * 4];
                float iv = invc_s[row];
                va.x *= iv; va.y *= iv; va.z *= iv; va.w *= iv;
            } else {
                uint4 u = *(const uint4*)&g_seg_max[(size_t)(tileM + row) * DIM + (kc - 4) * 64 + q * 4];
                if (cnt_s[row] > 0) {
                    va.x = dec_f(u.x); va.y = dec_f(u.y); va.z = dec_f(u.z); va.w = dec_f(u.w);
                } else {
                    va.x = va.y = va.z = va.w = 0.0f;
                }
            }
            __half2 h0 = __floats2half2_rn(va.x, va.y);
            __half2 h1 = __floats2half2_rn(va.z, va.w);
            uint32_t addr = (sb + P_OFF_XA + (uint32_t)row * 128u + (uint32_t)q * 8u) ^ RSWZ(row);
            sts8(addr, *(uint32_t*)&h0, *(uint32_t*)&h1);
        }
        // Wp chunk: 256 rows x 64 k fp16
#pragma unroll
        for (int i = 0; i < 8; i++) {
            int idx = i * 256 + t;
            int row = idx >> 3, q = idx & 7;
            uint4 v = ((const uint4*)g_Wph)[row * 64 + kc * 8 + q];
            uint32_t addr = (sb + P_OFF_B + (uint32_t)row * 128u + (uint32_t)q * 16u) ^ RSWZ(row);
            sts16(addr, v);
        }
        __syncthreads();

#pragma unroll
        for (int ks = 0; ks < 4; ks++) {
            const uint32_t koff = (uint32_t)ks * 32u;
            uint32_t a0[4], a1[4];
            ldmat_x4(a0, (a_base + koff) ^ xmask);
            ldmat_x4(a1, (a_base + 16u * 128u + koff) ^ xmask);
#pragma unroll
            for (int p = 0; p < 2; p++) {
                uint32_t bf[4];
                ldmat_x4(bf, (b_base + (uint32_t)p * 2048u + koff) ^ xmask);
                mma16816(acc[0][2 * p],     a0, bf[0], bf[2]);
                mma16816(acc[0][2 * p + 1], a0, bf[1], bf[3]);
                mma16816(acc[1][2 * p],     a1, bf[0], bf[2]);
                mma16816(acc[1][2 * p + 1], a1, bf[1], bf[3]);
            }
        }
    }

    // ---- stage out tile [32 x 256] fp32 (+bias) ----
    {
        const int r0 = lane >> 2;
        const int c0 = wn * 32 + 2 * (lane & 3);
#pragma unroll
        for (int mi = 0; mi < 2; mi++)
#pragma unroll
            for (int ni = 0; ni < 4; ni++) {
                int col = c0 + ni * 8;
                float bb0 = bp_s[col], bb1 = bp_s[col + 1];
                int rr = r0 + mi * 16;
                outs[rr * OUT_LD + col]           = acc[mi][ni][0] + bb0;
                outs[rr * OUT_LD + col + 1]       = acc[mi][ni][1] + bb1;
                outs[(rr + 8) * OUT_LD + col]     = acc[mi][ni][2] + bb0;
                outs[(rr + 8) * OUT_LD + col + 1] = acc[mi][ni][3] + bb1;
            }
    }
    __syncthreads();

    // ---- scatter rows [rowstart(tileM), rowstart(tileM+32)) with MLP=4 ----
    const int rstart = g_rowstart[tileM];
    const int rend   = g_rowstart[tileM + 32];
    const int cq     = t & 63;
    int r = rstart + (t >> 6);
    for (; r + 12 < rend; r += 16) {
        int s0 = __ldg(&bidx[r])      - tileM;
        int s1 = __ldg(&bidx[r +  4]) - tileM;
        int s2 = __ldg(&bidx[r +  8]) - tileM;
        int s3 = __ldg(&bidx[r + 12]) - tileM;
        float4 v0 = *(const float4*)&outs[s0 * OUT_LD + cq * 4];
        float4 v1 = *(const float4*)&outs[s1 * OUT_LD + cq * 4];
        float4 v2 = *(const float4*)&outs[s2 * OUT_LD + cq * 4];
        float4 v3 = *(const float4*)&outs[s3 * OUT_LD + cq * 4];
        out4[(size_t)r * 64 + cq]        = v0;
        out4[(size_t)(r +  4) * 64 + cq] = v1;
        out4[(size_t)(r +  8) * 64 + cq] = v2;
        out4[(size_t)(r + 12) * 64 + cq] = v3;
    }
    for (; r < rend; r += 4) {
        int s0 = __ldg(&bidx[r]) - tileM;
        out4[(size_t)r * 64 + cq] = *(const float4*)&outs[s0 * OUT_LD + cq * 4];
    }
}

// ---------------- launch -----------------------------------------------------
extern "C" void kernel_launch(void* const* d_in, const int* in_sizes, int n_in,
                              void* d_out, int out_size) {
    const float* x    = (const float*)d_in[0];
    const int*   bidx = (const int*)  d_in[1];
    const float* W1   = (const float*)d_in[2];
    const float* b1   = (const float*)d_in[3];
    const float* Wp   = (const float*)d_in[4];
    const float* bp   = (const float*)d_in[5];

    cudaFuncSetAttribute(gemm_pool_mma, cudaFuncAttributeMaxDynamicSharedMemorySize,
                         SMEM_A_BYTES);
    cudaFuncSetAttribute(proj_scatter, cudaFuncAttributeMaxDynamicSharedMemorySize,
                         SMEM_P_BYTES);

    init_kernel<<<NSEG * DIM / 256, 256>>>();
    wconv_kernel<<<384, 256>>>(W1, Wp);
    rowstart_kernel<<<NSEG / 256, 256>>>(bidx);
    xconv_kernel<<<32768, 256>>>(x);

    gemm_pool_mma<<<GRID_A, 512, SMEM_A_BYTES>>>(bidx, b1);

    proj_scatter<<<NSEG / 32, 256, SMEM_P_BYTES>>>(bidx, bp, (float4*)d_out);
}

// round 10
// speedup vs baseline: 1.4594x; 1.0195x over previous
#include <cuda_runtime.h>
#include <cuda_fp16.h>
#include <cstdint>

#define N_ROWS 524288
#define DIM 256
#define NSEG 8192
#define M_TILES 4096      // 128-row M tiles
#define GRID_A 148

// ---------------- scratch (device globals) ----------------------------------
__device__ float    g_seg_sum[NSEG * DIM];
__device__ unsigned g_seg_max[NSEG * DIM];
__device__ int      g_rowstart[NSEG + 1];
__device__ __half   g_W1h[DIM * DIM];
__device__ __half   g_Wph[DIM * 2 * DIM];
__device__ __half   g_xh[(size_t)N_ROWS * DIM];   // 268 MB fp16 copy of x

// ---------------- helpers ----------------------------------------------------
__device__ __forceinline__ uint32_t smem_u32(const void* p) {
    uint32_t a;
    asm("{ .reg .u64 t; cvta.to.shared.u64 t, %1; cvt.u32.u64 %0, t; }" : "=r"(a) : "l"(p));
    return a;
}
__device__ __forceinline__ void ldmat_x4(uint32_t r[4], uint32_t addr) {
    asm volatile("ldmatrix.sync.aligned.m8n8.x4.shared.b16 {%0,%1,%2,%3}, [%4];"
                 : "=r"(r[0]), "=r"(r[1]), "=r"(r[2]), "=r"(r[3]) : "r"(addr));
}
__device__ __forceinline__ void mma16816(float d[4], const uint32_t a[4],
                                         uint32_t b0, uint32_t b1) {
    asm volatile("mma.sync.aligned.m16n8k16.row.col.f32.f16.f16.f32 "
                 "{%0,%1,%2,%3}, {%4,%5,%6,%7}, {%8,%9}, {%0,%1,%2,%3};"
                 : "+f"(d[0]), "+f"(d[1]), "+f"(d[2]), "+f"(d[3])
                 : "r"(a[0]), "r"(a[1]), "r"(a[2]), "r"(a[3]), "r"(b0), "r"(b1));
}
__device__ __forceinline__ void sts8(uint32_t addr, uint32_t u0, uint32_t u1) {
    asm volatile("st.shared.v2.b32 [%0], {%1,%2};" :: "r"(addr), "r"(u0), "r"(u1) : "memory");
}
__device__ __forceinline__ void sts16(uint32_t addr, uint4 v) {
    asm volatile("st.shared.v4.b32 [%0], {%1,%2,%3,%4};"
                 :: "r"(addr), "r"(v.x), "r"(v.y), "r"(v.z), "r"(v.w) : "memory");
}
__device__ __forceinline__ void cpasync16(uint32_t dst, const void* src) {
    asm volatile("cp.async.cg.shared.global [%0], [%1], 16;" :: "r"(dst), "l"(src) : "memory");
}
#define CP_COMMIT() asm volatile("cp.async.commit_group;" ::: "memory")
#define CP_WAIT0()  asm volatile("cp.async.wait_group 0;"  ::: "memory")

__device__ __forceinline__ unsigned enc_f(float f) {
    unsigned i = __float_as_uint(f);
    return (i & 0x80000000u) ? ~i : (i | 0x80000000u);
}
__device__ __forceinline__ float dec_f(unsigned u) {
    return __uint_as_float((u & 0x80000000u) ? (u & 0x7FFFFFFFu) : ~u);
}
#define RSWZ(row) (((uint32_t)((row) & 7)) << 4)

// ---------------- kernel A smem layout (512B rows, swizzled) ----------------
#define OFF_W    0u          // 256 rows x 512B = 131072
#define OFF_A    131072u     // 128 rows x 512B = 65536
#define OFF_BIAS 196608u     // 1024
#define OFF_SEG  197632u     // 512
#define SMEM_A_BYTES 198144

// ---------------- proj smem layout (tile M=32) --------------------------------
#define P_OFF_B    0u        // Wp chunk: 256 x 128B = 32768
#define P_OFF_XA   32768u    // xpool chunk: 32 x 128B = 4096
#define P_OFF_OUT  36864u    // 32 x 260 x 4 = 33280
#define P_OFF_CNT  70144u    // 128
#define P_OFF_INV  70272u    // 128
#define P_OFF_BP   70400u    // 1024
#define SMEM_P_BYTES 71424
#define OUT_LD 260

// ---------------- prep: xconv (all blocks) + init/wconv/rowstart (role blocks)
__global__ void prep_kernel(const float* __restrict__ x,
                            const float* __restrict__ W1,
                            const float* __restrict__ Wp,
                            const int*   __restrict__ bidx)
{
    const int b = blockIdx.x;
    const int t = threadIdx.x;

    // ---- xconv: every block converts 1024 float4 of x ----
    {
        const float4* x4 = (const float4*)x;
        uint2* o = (uint2*)g_xh;
        int base = b * 1024 + t;
#pragma unroll
        for (int i = 0; i < 4; i++) {
            float4 v = x4[base + i * 256];
            __half2 h0 = __floats2half2_rn(v.x, v.y);
            __half2 h1 = __floats2half2_rn(v.z, v.w);
            o[base + i * 256] = make_uint2(*(uint32_t*)&h0, *(uint32_t*)&h1);
        }
    }

    // ---- role work on disjoint block ranges ----
    if (b < 8192) {                       // init: 8192 * 256 = NSEG*DIM
        int i = b * 256 + t;
        g_seg_sum[i] = 0.0f;
        g_seg_max[i] = 0u;
    } else if (b < 8192 + 384) {          // wconv: 384 * 256 = 98304 pairs
        int i = (b - 8192) * 256 + t;
        if (i < 32768) {
            float2 f = ((const float2*)W1)[i];
            ((__half2*)g_W1h)[i] = __floats2half2_rn(f.x, f.y);
        } else {
            int j = i - 32768;
            float2 f = ((const float2*)Wp)[j];
            ((__half2*)g_Wph)[j] = __floats2half2_rn(f.x, f.y);
        }
    } else if (b < 8192 + 384 + 32) {     // rowstart: 32 * 256 = NSEG
        int s = (b - 8192 - 384) * 256 + t;
        int lo = 0, hi = N_ROWS;
        while (lo < hi) {
            int mid = (lo + hi) >> 1;
            if (__ldg(&bidx[mid]) < s) lo = mid + 1; else hi = mid;
        }
        g_rowstart[s] = lo;
        if (s == 0) g_rowstart[NSEG] = N_ROWS;
    }
}

// ---------------- kernel A: HMMA GEMM + shuffle segmented reduce -------------
// 256 thr = 8 warps (2M x 4N); warp tile 64x64; tile 128x256; cp.async fp16.
__global__ void __launch_bounds__(256, 1) gemm_pool_mma(
    const int*   __restrict__ bidx,
    const float* __restrict__ b1)
{
    extern __shared__ char smem[];
    const uint32_t sb = smem_u32(smem);
    const int t    = threadIdx.x;
    const int w    = t >> 5;
    const int lane = t & 31;
    const int wm   = w >> 2;          // 0..1 (64-row band)
    const int wn   = w & 3;           // 0..3 (64-col band)

    float* bias_s = (float*)(smem + OFF_BIAS);
    int*   seg_s  = (int*)(smem + OFF_SEG);

    // ---- issue cp.async for first tile immediately ----
    {
        const int rowbase = blockIdx.x * 128;
#pragma unroll
        for (int j = 0; j < 16; j++) {
            int idx = j * 256 + t;           // 4096 16B chunks
            int r = idx >> 5, q = idx & 31;
            uint32_t dst = (sb + OFF_A + (uint32_t)r * 512u + (uint32_t)q * 16u) ^ RSWZ(r);
            cpasync16(dst, g_xh + (size_t)(rowbase + r) * DIM + q * 8);
        }
        CP_COMMIT();
        if (t < 128) seg_s[t] = bidx[rowbase + t];
    }

    bias_s[t] = b1[t];   // 256 threads cover 256 biases

    // ---- W1 fp16 -> SMEM [n][k] 512B rows, swizzled (once per CTA) ----
    {
        const uint4* wsrc = (const uint4*)g_W1h;   // 8192 uint4
#pragma unroll
        for (int j = 0; j < 32; j++) {
            int idx = j * 256 + t;
            int row = idx >> 5, q = idx & 31;
            uint32_t addr = (sb + OFF_W + (uint32_t)row * 512u + (uint32_t)q * 16u) ^ RSWZ(row);
            sts16(addr, wsrc[idx]);
        }
    }
    CP_WAIT0();
    __syncthreads();

    const uint32_t xmask  = RSWZ(lane);
    const uint32_t a_base = sb + OFF_A + (uint32_t)(wm * 64 + (lane & 15)) * 512u + (uint32_t)(lane >> 4) * 16u;
    const uint32_t b_base = sb + OFF_W + (uint32_t)(wn * 64 + (lane & 15)) * 512u + (uint32_t)(lane >> 4) * 16u;

    // bias for this thread's 16 columns (col = wn*64 + ni*8 + 2*(lane&3) + p)
    const int colbase = wn * 64 + 2 * (lane & 3);
    float bb[16];
#pragma unroll
    for (int i = 0; i < 16; i++) bb[i] = bias_s[colbase + (i >> 1) * 8 + (i & 1)];

    for (int tile = blockIdx.x; tile < M_TILES; tile += GRID_A) {
        // ---- HMMA mainloop: K = 256 in 16 steps; warp tile 64x64 ----
        float acc[4][8][4];
#pragma unroll
        for (int mi = 0; mi < 4; mi++)
#pragma unroll
            for (int ni = 0; ni < 8; ni++)
#pragma unroll
                for (int d = 0; d < 4; d++) acc[mi][ni][d] = 0.0f;

#pragma unroll 2
        for (int ks = 0; ks < 16; ks++) {
            const uint32_t koff = (uint32_t)ks * 32u;
            uint32_t af[4][4];
#pragma unroll
            for (int mi = 0; mi < 4; mi++)
                ldmat_x4(af[mi], (a_base + (uint32_t)mi * 8192u + koff) ^ xmask);
#pragma unroll
            for (int p = 0; p < 4; p++) {
                uint32_t bf[4];
                ldmat_x4(bf, (b_base + (uint32_t)p * 8192u + koff) ^ xmask);
#pragma unroll
                for (int mi = 0; mi < 4; mi++) {
                    mma16816(acc[mi][2 * p],     af[mi], bf[0], bf[2]);
                    mma16816(acc[mi][2 * p + 1], af[mi], bf[1], bf[3]);
                }
            }
        }
        __syncthreads();   // all warps done reading A

        // ---- prefetch next x tile via cp.async ----
        const int  ntile = tile + GRID_A;
        const bool more  = ntile < M_TILES;
        int segnext = 0;
        if (more) {
            const int nrow = ntile * 128;
#pragma unroll
            for (int j = 0; j < 16; j++) {
                int idx = j * 256 + t;
                int r = idx >> 5, q = idx & 31;
                uint32_t dst = (sb + OFF_A + (uint32_t)r * 512u + (uint32_t)q * 16u) ^ RSWZ(r);
                cpasync16(dst, g_xh + (size_t)(nrow + r) * DIM + q * 8);
            }
            if (t < 128) segnext = bidx[nrow + t];
        }
        CP_COMMIT();

        // ---- barrier-free epilogue: bias + shuffle segmented reduce ----
        {
#pragma unroll
            for (int mi = 0; mi < 4; mi++)
#pragma unroll
                for (int ni = 0; ni < 8; ni++)
#pragma unroll
                    for (int d = 0; d < 4; d++)
                        acc[mi][ni][d] += bb[ni * 2 + (d & 1)];

            float ps[16], pm[16];
            int pseg = -1;

#pragma unroll
            for (int b = 0; b < 8; b++) {
                const int mi = b >> 1, rh = b & 1;
                const int rb = wm * 64 + mi * 16 + rh * 8;
                const int seg0 = seg_s[rb];
                const int seg7 = seg_s[rb + 7];

                float v[16];
#pragma unroll
                for (int ni = 0; ni < 8; ni++) {
                    v[ni * 2]     = acc[mi][ni][2 * rh];
                    v[ni * 2 + 1] = acc[mi][ni][2 * rh + 1];
                }

                if (seg0 == seg7) {
                    // pure block (warp-uniform branch)
                    if (pseg == seg0) {
#pragma unroll
                        for (int i = 0; i < 16; i++) {
                            ps[i] += v[i];
                            pm[i] = fmaxf(pm[i], v[i]);
                        }
                    } else {
                        if (pseg >= 0) {
#pragma unroll
                            for (int r = 4; r <= 16; r <<= 1)
#pragma unroll
                                for (int i = 0; i < 16; i++) {
                                    ps[i] += __shfl_xor_sync(0xFFFFFFFFu, ps[i], r);
                                    pm[i] = fmaxf(pm[i], __shfl_xor_sync(0xFFFFFFFFu, pm[i], r));
                                }
                            unsigned gb = (unsigned)pseg * DIM + colbase;
                            if (lane < 4) {
#pragma unroll
                                for (int i = 0; i < 16; i++)
                                    atomicAdd(&g_seg_sum[gb + (i >> 1) * 8 + (i & 1)], ps[i]);
                            } else if (lane < 8) {
#pragma unroll
                                for (int i = 0; i < 16; i++)
                                    atomicMax(&g_seg_max[gb + (i >> 1) * 8 + (i & 1)], enc_f(pm[i]));
                            }
                        }
#pragma unroll
                        for (int i = 0; i < 16; i++) { ps[i] = v[i]; pm[i] = v[i]; }
                        pseg = seg0;
                    }
                } else {
                    // impure block: one row per thread, direct atomics
                    const int myseg = seg_s[rb + (lane >> 2)];
                    unsigned gb = (unsigned)myseg * DIM + colbase;
#pragma unroll
                    for (int i = 0; i < 16; i++) {
                        atomicAdd(&g_seg_sum[gb + (i >> 1) * 8 + (i & 1)], v[i]);
                        atomicMax(&g_seg_max[gb + (i >> 1) * 8 + (i & 1)], enc_f(v[i]));
                    }
                }
            }
            if (pseg >= 0) {
#pragma unroll
                for (int r = 4; r <= 16; r <<= 1)
#pragma unroll
                    for (int i = 0; i < 16; i++) {
                        ps[i] += __shfl_xor_sync(0xFFFFFFFFu, ps[i], r);
                        pm[i] = fmaxf(pm[i], __shfl_xor_sync(0xFFFFFFFFu, pm[i], r));
                    }
                unsigned gb = (unsigned)pseg * DIM + colbase;
                if (lane < 4) {
#pragma unroll
                    for (int i = 0; i < 16; i++)
                        atomicAdd(&g_seg_sum[gb + (i >> 1) * 8 + (i & 1)], ps[i]);
                } else if (lane < 8) {
#pragma unroll
                    for (int i = 0; i < 16; i++)
                        atomicMax(&g_seg_max[gb + (i >> 1) * 8 + (i & 1)], enc_f(pm[i]));
                }
            }
        }

        CP_WAIT0();
        __syncthreads();   // A(next) ready; all seg_s reads done
        if (more && t < 128) seg_s[t] = segnext;  // ordered before next epilogue by next post-mainloop sync
    }
}

// ---------------- proj: HMMA fp16 GEMM + fused MLP-4 scatter ------------------
// 256 CTAs x 256 thr (2/SM); tile M=32 segs, N=256 cols, K=512 in 8 chunks.
__global__ void __launch_bounds__(256, 2) proj_scatter(
    const int*   __restrict__ bidx,
    const float* __restrict__ bp,
    float4*      __restrict__ out4)
{
    extern __shared__ char smem[];
    const uint32_t sb = smem_u32(smem);
    const int t    = threadIdx.x;
    const int w    = t >> 5;
    const int lane = t & 31;
    const int wn   = w;              // 0..7, 32-col band
    const int tileM = blockIdx.x * 32;

    int*   cnt_s  = (int*)(smem + P_OFF_CNT);
    float* invc_s = (float*)(smem + P_OFF_INV);
    float* bp_s   = (float*)(smem + P_OFF_BP);
    float* outs   = (float*)(smem + P_OFF_OUT);

    if (t < 32) {
        int cn = g_rowstart[tileM + t + 1] - g_rowstart[tileM + t];
        cnt_s[t]  = cn;
        invc_s[t] = 1.0f / (float)max(cn, 1);
    }
    bp_s[t] = bp[t];

    const uint32_t xmask  = RSWZ(lane);
    const uint32_t a_base = sb + P_OFF_XA + (uint32_t)(lane & 15) * 128u + (uint32_t)(lane >> 4) * 16u;
    const uint32_t b_base = sb + P_OFF_B  + (uint32_t)(wn * 32 + (lane & 15)) * 128u + (uint32_t)(lane >> 4) * 16u;

    float acc[2][4][4];
#pragma unroll
    for (int mi = 0; mi < 2; mi++)
#pragma unroll
        for (int ni = 0; ni < 4; ni++)
#pragma unroll
            for (int d = 0; d < 4; d++) acc[mi][ni][d] = 0.0f;

#pragma unroll 1
    for (int kc = 0; kc < 8; kc++) {
        __syncthreads();

        // xpool chunk: 32 rows x 64 k -> fp16 swizzled
#pragma unroll
        for (int i = 0; i < 2; i++) {
            int idx = i * 256 + t;
            int row = idx >> 4, q = idx & 15;
            float4 va;
            if (kc < 4) {
                va = *(const float4*)&g_seg_sum[(size_t)(tileM + row) * DIM + kc * 64 + q * 4];
                float iv = invc_s[row];
                va.x *= iv; va.y *= iv; va.z *= iv; va.w *= iv;
            } else {
                uint4 u = *(const uint4*)&g_seg_max[(size_t)(tileM + row) * DIM + (kc - 4) * 64 + q * 4];
                if (cnt_s[row] > 0) {
                    va.x = dec_f(u.x); va.y = dec_f(u.y); va.z = dec_f(u.z); va.w = dec_f(u.w);
                } else {
                    va.x = va.y = va.z = va.w = 0.0f;
                }
            }
            __half2 h0 = __floats2half2_rn(va.x, va.y);
            __half2 h1 = __floats2half2_rn(va.z, va.w);
            uint32_t addr = (sb + P_OFF_XA + (uint32_t)row * 128u + (uint32_t)q * 8u) ^ RSWZ(row);
            sts8(addr, *(uint32_t*)&h0, *(uint32_t*)&h1);
        }
        // Wp chunk: 256 rows x 64 k fp16
#pragma unroll
        for (int i = 0; i < 8; i++) {
            int idx = i * 256 + t;
            int row = idx >> 3, q = idx & 7;
            uint4 v = ((const uint4*)g_Wph)[row * 64 + kc * 8 + q];
            uint32_t addr = (sb + P_OFF_B + (uint32_t)row * 128u + (uint32_t)q * 16u) ^ RSWZ(row);
            sts16(addr, v);
        }
        __syncthreads();

#pragma unroll
        for (int ks = 0; ks < 4; ks++) {
            const uint32_t koff = (uint32_t)ks * 32u;
            uint32_t a0[4], a1[4];
            ldmat_x4(a0, (a_base + koff) ^ xmask);
            ldmat_x4(a1, (a_base + 16u * 128u + koff) ^ xmask);
#pragma unroll
            for (int p = 0; p < 2; p++) {
                uint32_t bf[4];
                ldmat_x4(bf, (b_base + (uint32_t)p * 2048u + koff) ^ xmask);
                mma16816(acc[0][2 * p],     a0, bf[0], bf[2]);
                mma16816(acc[0][2 * p + 1], a0, bf[1], bf[3]);
                mma16816(acc[1][2 * p],     a1, bf[0], bf[2]);
                mma16816(acc[1][2 * p + 1], a1, bf[1], bf[3]);
            }
        }
    }

    // ---- stage out tile [32 x 256] fp32 (+bias) ----
    {
        const int r0 = lane >> 2;
        const int c0 = wn * 32 + 2 * (lane & 3);
#pragma unroll
        for (int mi = 0; mi < 2; mi++)
#pragma unroll
            for (int ni = 0; ni < 4; ni++) {
                int col = c0 + ni * 8;
                float bb0 = bp_s[col], bb1 = bp_s[col + 1];
                int rr = r0 + mi * 16;
                outs[rr * OUT_LD + col]           = acc[mi][ni][0] + bb0;
                outs[rr * OUT_LD + col + 1]       = acc[mi][ni][1] + bb1;
                outs[(rr + 8) * OUT_LD + col]     = acc[mi][ni][2] + bb0;
                outs[(rr + 8) * OUT_LD + col + 1] = acc[mi][ni][3] + bb1;
            }
    }
    __syncthreads();

    // ---- scatter rows [rowstart(tileM), rowstart(tileM+32)) with MLP=4 ----
    const int rstart = g_rowstart[tileM];
    const int rend   = g_rowstart[tileM + 32];
    const int cq     = t & 63;
    int r = rstart + (t >> 6);
    for (; r + 12 < rend; r += 16) {
        int s0 = __ldg(&bidx[r])      - tileM;
        int s1 = __ldg(&bidx[r +  4]) - tileM;
        int s2 = __ldg(&bidx[r +  8]) - tileM;
        int s3 = __ldg(&bidx[r + 12]) - tileM;
        float4 v0 = *(const float4*)&outs[s0 * OUT_LD + cq * 4];
        float4 v1 = *(const float4*)&outs[s1 * OUT_LD + cq * 4];
        float4 v2 = *(const float4*)&outs[s2 * OUT_LD + cq * 4];
        float4 v3 = *(const float4*)&outs[s3 * OUT_LD + cq * 4];
        out4[(size_t)r * 64 + cq]        = v0;
        out4[(size_t)(r +  4) * 64 + cq] = v1;
        out4[(size_t)(r +  8) * 64 + cq] = v2;
        out4[(size_t)(r + 12) * 64 + cq] = v3;
    }
    for (; r < rend; r += 4) {
        int s0 = __ldg(&bidx[r]) - tileM;
        out4[(size_t)r * 64 + cq] = *(const float4*)&outs[s0 * OUT_LD + cq * 4];
    }
}

// ---------------- launch -----------------------------------------------------
extern "C" void kernel_launch(void* const* d_in, const int* in_sizes, int n_in,
                              void* d_out, int out_size) {
    const float* x    = (const float*)d_in[0];
    const int*   bidx = (const int*)  d_in[1];
    const float* W1   = (const float*)d_in[2];
    const float* b1   = (const float*)d_in[3];
    const float* Wp   = (const float*)d_in[4];
    const float* bp   = (const float*)d_in[5];

    cudaFuncSetAttribute(gemm_pool_mma, cudaFuncAttributeMaxDynamicSharedMemorySize,
                         SMEM_A_BYTES);
    cudaFuncSetAttribute(proj_scatter, cudaFuncAttributeMaxDynamicSharedMemorySize,
                         SMEM_P_BYTES);

    prep_kernel<<<32768, 256>>>(x, W1, Wp, bidx);

    gemm_pool_mma<<<GRID_A, 256, SMEM_A_BYTES>>>(bidx, b1);

    proj_scatter<<<NSEG / 32, 256, SMEM_P_BYTES>>>(bidx, bp, (float4*)d_out);
}